// round 6
// baseline (speedup 1.0000x reference)
#include <cuda_runtime.h>
#include <cstdint>

// Problem constants
#define BB    8
#define LSEQ  4096
#define DD    256
#define MTOT  (BB * LSEQ)          // 32768 rows for the projection GEMMs

constexpr float DECAY     = 0.9f;
constexpr float LR        = 0.1f;
constexpr int   SCHUNK    = 16;
constexpr float DEC16     = 0.1853020188851841f;   // 0.9^16
constexpr float INV_DECAY = 1.1111111111111112f;   // 1/0.9

// Scratch (allocation-free rule: __device__ globals)
__device__ float g_k[MTOT * DD];
__device__ float g_v[MTOT * DD];
__device__ float g_q[MTOT * DD];
__device__ float g_y[MTOT * DD];

// ---------------------------------------------------------------------------
// Kernel 1: fused QKV projection.
//   g_k[m][n] = sum_d x[m][d] * Wk[n][d] + bk[n]   (torch Linear: x @ W^T + b)
//   same for g_v (Wv,bv) and g_q (Wq,bq).
// 64x64 tile per CTA, 256 threads, 4x4 microtile per thread per weight.
// ---------------------------------------------------------------------------
__global__ __launch_bounds__(256) void qkv_kernel(
    const float* __restrict__ x,
    const float* __restrict__ Wk, const float* __restrict__ bk,
    const float* __restrict__ Wv, const float* __restrict__ bv,
    const float* __restrict__ Wq, const float* __restrict__ bq)
{
    __shared__ float As[16][68];        // x tile, transposed: As[d][m]
    __shared__ float Bs[3][16][68];     // weight tiles, transposed: Bs[w][d][n]

    const int m0  = blockIdx.x * 64;
    const int n0  = blockIdx.y * 64;
    const int tid = threadIdx.x;

    const int lrow = tid & 63;          // staging: row within tile
    const int ld4  = (tid >> 6) << 2;   // staging: d-offset {0,4,8,12}
    const int tm   = (tid >> 4) << 2;   // compute: row group within tile
    const int tn   = (tid & 15) << 2;   // compute: col group within tile

    float acc[3][4][4];
#pragma unroll
    for (int w = 0; w < 3; ++w)
#pragma unroll
        for (int i = 0; i < 4; ++i)
#pragma unroll
            for (int j = 0; j < 4; ++j) acc[w][i][j] = 0.0f;

    const float* Ws[3] = {Wk, Wv, Wq};

    for (int d0 = 0; d0 < DD; d0 += 16) {
        // stage x tile (transpose into As[d][m])
        {
            float4 xa = *(const float4*)(x + (size_t)(m0 + lrow) * DD + d0 + ld4);
            As[ld4 + 0][lrow] = xa.x;
            As[ld4 + 1][lrow] = xa.y;
            As[ld4 + 2][lrow] = xa.z;
            As[ld4 + 3][lrow] = xa.w;
        }
        // stage 3 weight tiles
#pragma unroll
        for (int w = 0; w < 3; ++w) {
            float4 wa = *(const float4*)(Ws[w] + (size_t)(n0 + lrow) * DD + d0 + ld4);
            Bs[w][ld4 + 0][lrow] = wa.x;
            Bs[w][ld4 + 1][lrow] = wa.y;
            Bs[w][ld4 + 2][lrow] = wa.z;
            Bs[w][ld4 + 3][lrow] = wa.w;
        }
        __syncthreads();

#pragma unroll
        for (int kk = 0; kk < 16; ++kk) {
            float4 a4 = *(const float4*)&As[kk][tm];
            float a[4] = {a4.x, a4.y, a4.z, a4.w};
#pragma unroll
            for (int w = 0; w < 3; ++w) {
                float4 b4 = *(const float4*)&Bs[w][kk][tn];
                float bb[4] = {b4.x, b4.y, b4.z, b4.w};
#pragma unroll
                for (int i = 0; i < 4; ++i)
#pragma unroll
                    for (int j = 0; j < 4; ++j)
                        acc[w][i][j] = fmaf(a[i], bb[j], acc[w][i][j]);
            }
        }
        __syncthreads();
    }

    // epilogue: add bias, write out
    float* outs[3] = {g_k, g_v, g_q};
    const float* biases[3] = {bk, bv, bq};
#pragma unroll
    for (int w = 0; w < 3; ++w) {
        float4 bias4 = *(const float4*)(biases[w] + n0 + tn);
        float bb[4] = {bias4.x, bias4.y, bias4.z, bias4.w};
#pragma unroll
        for (int i = 0; i < 4; ++i) {
            float4 r;
            r.x = acc[w][i][0] + bb[0];
            r.y = acc[w][i][1] + bb[1];
            r.z = acc[w][i][2] + bb[2];
            r.w = acc[w][i][3] + bb[3];
            *(float4*)(outs[w] + (size_t)(m0 + tm + i) * DD + n0 + tn) = r;
        }
    }
}

// ---------------------------------------------------------------------------
// Kernel 2: sequential Hebbian scan.
// Grid: (16 column-groups, 8 batches), 256 threads (8 warps).
// Warp w owns 2 columns (j0, j0+1); lane owns 8 contiguous rows.
// Decay folded algebraically into k/q scaling over 16-step chunks:
//   U_s = lambda*A_base + sum_{u<=s} eta*lambda^{-u} k_u v_u^T
//   A_{t0+s} = lambda^s * U_s,  y = (lambda^s q)^T U_s
//   at chunk end: U <- lambda^16 * U  (restores the invariant U = lambda*A)
// One FFMA per state element for update, one for readout.
// ---------------------------------------------------------------------------
__global__ __launch_bounds__(256) void scan_kernel(
    const float* __restrict__ state,   // (B, D, D) initial state
    float* __restrict__ fstate)        // (B, D, D) final state output
{
    const int b    = blockIdx.y;
    const int w    = threadIdx.x >> 5;
    const int lane = threadIdx.x & 31;
    const int j0   = blockIdx.x * 16 + w * 2;   // two columns j0, j0+1
    const int i0   = lane * 8;                  // 8 contiguous rows

    float Ux[8], Uy[8];
#pragma unroll
    for (int r = 0; r < 8; ++r) {
        float2 s2 = *(const float2*)(state + ((size_t)(b * DD + i0 + r)) * DD + j0);
        Ux[r] = DECAY * s2.x;   // U = lambda * A_init
        Uy[r] = DECAY * s2.y;
    }

    const float* kptr = g_k + (size_t)b * LSEQ * DD + i0;
    const float* qptr = g_q + (size_t)b * LSEQ * DD + i0;
    const float* vptr = g_v + (size_t)b * LSEQ * DD + j0;
    float*       yptr = g_y + (size_t)b * LSEQ * DD + j0;

    for (int c = 0; c < LSEQ / SCHUNK; ++c) {
        float kscale = LR;      // eta * lambda^{-s}
        float qscale = 1.0f;    // lambda^{s}
#pragma unroll
        for (int s = 0; s < SCHUNK; ++s) {
            float4 k0 = *(const float4*)(kptr);
            float4 k1 = *(const float4*)(kptr + 4);
            float4 q0 = *(const float4*)(qptr);
            float4 q1 = *(const float4*)(qptr + 4);
            float2 v2 = *(const float2*)(vptr);
            kptr += DD; qptr += DD; vptr += DD;

            // fold (eta * lambda^{-s}) into the 2 v values, not the 8 k values
            float v0 = v2.x * kscale;
            float v1 = v2.y * kscale;

            float kr[8] = {k0.x, k0.y, k0.z, k0.w, k1.x, k1.y, k1.z, k1.w};
            float qr[8] = {q0.x, q0.y, q0.z, q0.w, q1.x, q1.y, q1.z, q1.w};

            float p0 = 0.0f, p1 = 0.0f;
#pragma unroll
            for (int r = 0; r < 8; ++r) {
                Ux[r] = fmaf(kr[r], v0, Ux[r]);     // update (post-update state)
                Uy[r] = fmaf(kr[r], v1, Uy[r]);
                p0 = fmaf(qr[r], Ux[r], p0);        // readout partial
                p1 = fmaf(qr[r], Uy[r], p1);
            }
            // reduce 32 lanes (rows) -> 2 column sums
#pragma unroll
            for (int off = 16; off; off >>= 1) {
                p0 += __shfl_xor_sync(0xffffffffu, p0, off);
                p1 += __shfl_xor_sync(0xffffffffu, p1, off);
            }
            if (lane == 0) {
                *(float2*)yptr = make_float2(p0 * qscale, p1 * qscale);
            }
            yptr += DD;
            kscale *= INV_DECAY;
            qscale *= DECAY;
        }
        // restore invariant for next chunk: U <- lambda^16 * U (= lambda * A)
#pragma unroll
        for (int r = 0; r < 8; ++r) { Ux[r] *= DEC16; Uy[r] *= DEC16; }
    }

    // final state: A_final = U / lambda
#pragma unroll
    for (int r = 0; r < 8; ++r) {
        *(float2*)(fstate + ((size_t)(b * DD + i0 + r)) * DD + j0) =
            make_float2(Ux[r] * INV_DECAY, Uy[r] * INV_DECAY);
    }
}

// ---------------------------------------------------------------------------
// Kernel 3: output projection. out[m][n] = sum_d g_y[m][d]*Wo[n][d] + bo[n]
// ---------------------------------------------------------------------------
__global__ __launch_bounds__(256) void out_kernel(
    const float* __restrict__ Wo, const float* __restrict__ bo,
    float* __restrict__ out)
{
    __shared__ float As[16][68];
    __shared__ float Bs2[16][68];

    const int m0  = blockIdx.x * 64;
    const int n0  = blockIdx.y * 64;
    const int tid = threadIdx.x;

    const int lrow = tid & 63;
    const int ld4  = (tid >> 6) << 2;
    const int tm   = (tid >> 4) << 2;
    const int tn   = (tid & 15) << 2;

    float acc[4][4];
#pragma unroll
    for (int i = 0; i < 4; ++i)
#pragma unroll
        for (int j = 0; j < 4; ++j) acc[i][j] = 0.0f;

    for (int d0 = 0; d0 < DD; d0 += 16) {
        {
            float4 xa = *(const float4*)(g_y + (size_t)(m0 + lrow) * DD + d0 + ld4);
            As[ld4 + 0][lrow] = xa.x;
            As[ld4 + 1][lrow] = xa.y;
            As[ld4 + 2][lrow] = xa.z;
            As[ld4 + 3][lrow] = xa.w;
        }
        {
            float4 wa = *(const float4*)(Wo + (size_t)(n0 + lrow) * DD + d0 + ld4);
            Bs2[ld4 + 0][lrow] = wa.x;
            Bs2[ld4 + 1][lrow] = wa.y;
            Bs2[ld4 + 2][lrow] = wa.z;
            Bs2[ld4 + 3][lrow] = wa.w;
        }
        __syncthreads();

#pragma unroll
        for (int kk = 0; kk < 16; ++kk) {
            float4 a4 = *(const float4*)&As[kk][tm];
            float4 b4 = *(const float4*)&Bs2[kk][tn];
            float a[4]  = {a4.x, a4.y, a4.z, a4.w};
            float bb[4] = {b4.x, b4.y, b4.z, b4.w};
#pragma unroll
            for (int i = 0; i < 4; ++i)
#pragma unroll
                for (int j = 0; j < 4; ++j)
                    acc[i][j] = fmaf(a[i], bb[j], acc[i][j]);
        }
        __syncthreads();
    }

    float4 bias4 = *(const float4*)(bo + n0 + tn);
    float bb[4] = {bias4.x, bias4.y, bias4.z, bias4.w};
#pragma unroll
    for (int i = 0; i < 4; ++i) {
        float4 r;
        r.x = acc[i][0] + bb[0];
        r.y = acc[i][1] + bb[1];
        r.z = acc[i][2] + bb[2];
        r.w = acc[i][3] + bb[3];
        *(float4*)(out + (size_t)(m0 + tm + i) * DD + n0 + tn) = r;
    }
}

// ---------------------------------------------------------------------------
// Launch: inputs in metadata order:
//   0:x 1:state 2:Wk 3:bk 4:Wv 5:bv 6:Wq 7:bq 8:Wo 9:bo
// Output: out (B*L*D floats) followed by final_state (B*D*D floats).
// ---------------------------------------------------------------------------
extern "C" void kernel_launch(void* const* d_in, const int* in_sizes, int n_in,
                              void* d_out, int out_size)
{
    const float* x     = (const float*)d_in[0];
    const float* state = (const float*)d_in[1];
    const float* Wk    = (const float*)d_in[2];
    const float* bk    = (const float*)d_in[3];
    const float* Wv    = (const float*)d_in[4];
    const float* bv    = (const float*)d_in[5];
    const float* Wq    = (const float*)d_in[6];
    const float* bq    = (const float*)d_in[7];
    const float* Wo    = (const float*)d_in[8];
    const float* bo    = (const float*)d_in[9];

    float* out    = (float*)d_out;
    float* fstate = out + (size_t)MTOT * DD;

    dim3 gemm_grid(MTOT / 64, DD / 64);   // (512, 4)
    qkv_kernel<<<gemm_grid, 256>>>(x, Wk, bk, Wv, bv, Wq, bq);

    dim3 scan_grid(16, BB);               // 128 CTAs: 16 col-groups x 8 batches
    scan_kernel<<<scan_grid, 256>>>(state, fstate);

    out_kernel<<<gemm_grid, 256>>>(Wo, bo, out);
}

// round 7
// speedup vs baseline: 3.0514x; 3.0514x over previous
#include <cuda_runtime.h>
#include <cstdint>

// Problem constants
#define BB    8
#define LSEQ  4096
#define DD    256
#define MTOT  (BB * LSEQ)          // 32768 rows for the projection GEMMs

constexpr float DECAY     = 0.9f;
constexpr float LR        = 0.1f;
constexpr int   SCHUNK    = 16;
constexpr int   NCHUNK    = LSEQ / SCHUNK;         // 256
constexpr float DEC16     = 0.1853020188851841f;   // 0.9^16
constexpr float INV_DECAY = 1.1111111111111112f;   // 1/0.9

// Scratch (allocation-free rule: __device__ globals)
__device__ float g_k[MTOT * DD];
__device__ float g_v[MTOT * DD];
__device__ float g_q[MTOT * DD];
__device__ float g_y[MTOT * DD];

// ---------------------------------------------------------------------------
// cp.async helpers (sm_103a: LDGSTS)
// ---------------------------------------------------------------------------
__device__ __forceinline__ void cp_async16(void* smem_dst, const void* gmem_src) {
    unsigned d = (unsigned)__cvta_generic_to_shared(smem_dst);
    asm volatile("cp.async.cg.shared.global [%0], [%1], 16;\n" :: "r"(d), "l"(gmem_src));
}
__device__ __forceinline__ void cp_async_commit() {
    asm volatile("cp.async.commit_group;\n");
}
__device__ __forceinline__ void cp_async_wait1() {
    asm volatile("cp.async.wait_group 1;\n");
}

// ---------------------------------------------------------------------------
// Kernel 1: fused QKV projection (measured: at fp32 FFMA roofline, 364us).
// ---------------------------------------------------------------------------
__global__ __launch_bounds__(256) void qkv_kernel(
    const float* __restrict__ x,
    const float* __restrict__ Wk, const float* __restrict__ bk,
    const float* __restrict__ Wv, const float* __restrict__ bv,
    const float* __restrict__ Wq, const float* __restrict__ bq)
{
    __shared__ float As[16][68];        // x tile, transposed: As[d][m]
    __shared__ float Bs[3][16][68];     // weight tiles, transposed: Bs[w][d][n]

    const int m0  = blockIdx.x * 64;
    const int n0  = blockIdx.y * 64;
    const int tid = threadIdx.x;

    const int lrow = tid & 63;          // staging: row within tile
    const int ld4  = (tid >> 6) << 2;   // staging: d-offset {0,4,8,12}
    const int tm   = (tid >> 4) << 2;   // compute: row group within tile
    const int tn   = (tid & 15) << 2;   // compute: col group within tile

    float acc[3][4][4];
#pragma unroll
    for (int w = 0; w < 3; ++w)
#pragma unroll
        for (int i = 0; i < 4; ++i)
#pragma unroll
            for (int j = 0; j < 4; ++j) acc[w][i][j] = 0.0f;

    const float* Ws[3] = {Wk, Wv, Wq};

    for (int d0 = 0; d0 < DD; d0 += 16) {
        {
            float4 xa = *(const float4*)(x + (size_t)(m0 + lrow) * DD + d0 + ld4);
            As[ld4 + 0][lrow] = xa.x;
            As[ld4 + 1][lrow] = xa.y;
            As[ld4 + 2][lrow] = xa.z;
            As[ld4 + 3][lrow] = xa.w;
        }
#pragma unroll
        for (int w = 0; w < 3; ++w) {
            float4 wa = *(const float4*)(Ws[w] + (size_t)(n0 + lrow) * DD + d0 + ld4);
            Bs[w][ld4 + 0][lrow] = wa.x;
            Bs[w][ld4 + 1][lrow] = wa.y;
            Bs[w][ld4 + 2][lrow] = wa.z;
            Bs[w][ld4 + 3][lrow] = wa.w;
        }
        __syncthreads();

#pragma unroll
        for (int kk = 0; kk < 16; ++kk) {
            float4 a4 = *(const float4*)&As[kk][tm];
            float a[4] = {a4.x, a4.y, a4.z, a4.w};
#pragma unroll
            for (int w = 0; w < 3; ++w) {
                float4 b4 = *(const float4*)&Bs[w][kk][tn];
                float bb[4] = {b4.x, b4.y, b4.z, b4.w};
#pragma unroll
                for (int i = 0; i < 4; ++i)
#pragma unroll
                    for (int j = 0; j < 4; ++j)
                        acc[w][i][j] = fmaf(a[i], bb[j], acc[w][i][j]);
            }
        }
        __syncthreads();
    }

    float* outs[3] = {g_k, g_v, g_q};
    const float* biases[3] = {bk, bv, bq};
#pragma unroll
    for (int w = 0; w < 3; ++w) {
        float4 bias4 = *(const float4*)(biases[w] + n0 + tn);
        float bb[4] = {bias4.x, bias4.y, bias4.z, bias4.w};
#pragma unroll
        for (int i = 0; i < 4; ++i) {
            float4 r;
            r.x = acc[w][i][0] + bb[0];
            r.y = acc[w][i][1] + bb[1];
            r.z = acc[w][i][2] + bb[2];
            r.w = acc[w][i][3] + bb[3];
            *(float4*)(outs[w] + (size_t)(m0 + tm + i) * DD + n0 + tn) = r;
        }
    }
}

// ---------------------------------------------------------------------------
// Kernel 2: sequential Hebbian scan, v2: SMEM-staged, cp.async double-buffered.
//
// Grid (16, 8) = 128 CTAs (1/SM), 256 threads (8 warps).
// Warp w owns columns {j0, j0+1}; lane owns 8 contiguous rows.
//
// Per 16-step chunk: bulk-coalesced cp.async of k (16KB), q (16KB) and the
// CTA's 16 v-columns (1KB) into a double-buffered SMEM window; compute reads
// are LDS (conflict-free 128B phases), eliminating the 8x-redundant per-warp
// global loads that made v1 latency-bound (~1600 cyc/step).
//
// Decay folded algebraically per chunk (unchanged math, rel_err 8e-7):
//   U_s = lambda*A_base + sum_{u<=s} eta*lambda^{-u} k_u v_u^T
//   A_{t0+s} = lambda^s * U_s,  y = (lambda^s q)^T U_s
//   chunk end: U <- lambda^16 * U
// ---------------------------------------------------------------------------
__global__ __launch_bounds__(256) void scan_kernel(
    const float* __restrict__ state,   // (B, D, D) initial state
    float* __restrict__ fstate)        // (B, D, D) final state output
{
    extern __shared__ float smem[];
    // layout: ksh[2][16][256] | qsh[2][16][256] | vsh[2][16][16]
    float* ksh = smem;                 // 8192 floats
    float* qsh = smem + 8192;          // 8192 floats
    float* vsh = smem + 16384;         // 512 floats

    const int b    = blockIdx.y;
    const int tid  = threadIdx.x;
    const int w    = tid >> 5;
    const int lane = tid & 31;
    const int jb   = blockIdx.x * 16;           // CTA's 16-column base
    const int j0   = jb + w * 2;                // warp's two columns
    const int i0   = lane * 8;                  // 8 contiguous rows

    const float* kg = g_k + (size_t)b * LSEQ * DD;
    const float* qg = g_q + (size_t)b * LSEQ * DD;
    const float* vg = g_v + (size_t)b * LSEQ * DD + jb;
    float*       yg = g_y + (size_t)b * LSEQ * DD + j0;

    // ---- chunk loader: chunk c -> buffer nb ----
    auto load_chunk = [&](int c, int nb) {
        // k, q: contiguous 4096-float (16KB) regions; 256 thr x 4 x 16B
        const float* ks = kg + (size_t)c * (SCHUNK * DD);
        const float* qs = qg + (size_t)c * (SCHUNK * DD);
        float* kd = ksh + nb * 4096;
        float* qd = qsh + nb * 4096;
#pragma unroll
        for (int i = 0; i < 4; ++i) {
            int off = i * 1024 + tid * 4;
            cp_async16(kd + off, ks + off);
            cp_async16(qd + off, qs + off);
        }
        // v: 16 steps x 16 cols; 64 threads x 16B
        if (tid < 64) {
            int s  = tid >> 2;
            int p4 = (tid & 3) * 4;
            cp_async16(vsh + nb * 256 + s * 16 + p4,
                       vg + (size_t)(c * SCHUNK + s) * DD + p4);
        }
    };

    // ---- init state registers: U = lambda * A_init ----
    float Ux[8], Uy[8];
#pragma unroll
    for (int r = 0; r < 8; ++r) {
        float2 s2 = *(const float2*)(state + ((size_t)(b * DD + i0 + r)) * DD + j0);
        Ux[r] = DECAY * s2.x;
        Uy[r] = DECAY * s2.y;
    }

    // prologue: prefetch chunk 0
    load_chunk(0, 0);
    cp_async_commit();

    for (int c = 0; c < NCHUNK; ++c) {
        const int buf = c & 1;
        if (c + 1 < NCHUNK) load_chunk(c + 1, (c + 1) & 1);
        cp_async_commit();          // empty group on last iter keeps wait math uniform
        cp_async_wait1();           // chunk c resident (per-thread)
        __syncthreads();            // visible CTA-wide

        const float* kc = ksh + buf * 4096 + i0;
        const float* qc = qsh + buf * 4096 + i0;
        const float* vc = vsh + buf * 256 + w * 2;

        float kscale = LR;          // eta * lambda^{-s}
        float qscale = 1.0f;        // lambda^{s}
        float* yp = yg + (size_t)c * (SCHUNK * DD);
#pragma unroll
        for (int s = 0; s < SCHUNK; ++s) {
            float4 k0 = *(const float4*)(kc + s * DD);
            float4 k1 = *(const float4*)(kc + s * DD + 4);
            float4 q0 = *(const float4*)(qc + s * DD);
            float4 q1 = *(const float4*)(qc + s * DD + 4);
            float2 v2 = *(const float2*)(vc + s * 16);

            float v0 = v2.x * kscale;
            float v1 = v2.y * kscale;

            float kr[8] = {k0.x, k0.y, k0.z, k0.w, k1.x, k1.y, k1.z, k1.w};
            float qr[8] = {q0.x, q0.y, q0.z, q0.w, q1.x, q1.y, q1.z, q1.w};

            float p0 = 0.0f, p1 = 0.0f;
#pragma unroll
            for (int r = 0; r < 8; ++r) {
                Ux[r] = fmaf(kr[r], v0, Ux[r]);     // update (post-update state)
                Uy[r] = fmaf(kr[r], v1, Uy[r]);
                p0 = fmaf(qr[r], Ux[r], p0);        // readout partial
                p1 = fmaf(qr[r], Uy[r], p1);
            }
#pragma unroll
            for (int off = 16; off; off >>= 1) {
                p0 += __shfl_xor_sync(0xffffffffu, p0, off);
                p1 += __shfl_xor_sync(0xffffffffu, p1, off);
            }
            if (lane == 0) {
                *(float2*)(yp) = make_float2(p0 * qscale, p1 * qscale);
            }
            yp += DD;
            kscale *= INV_DECAY;
            qscale *= DECAY;
        }
#pragma unroll
        for (int r = 0; r < 8; ++r) { Ux[r] *= DEC16; Uy[r] *= DEC16; }

        __syncthreads();            // protect buf before it is overwritten
    }

    // final state: A_final = U / lambda
#pragma unroll
    for (int r = 0; r < 8; ++r) {
        *(float2*)(fstate + ((size_t)(b * DD + i0 + r)) * DD + j0) =
            make_float2(Ux[r] * INV_DECAY, Uy[r] * INV_DECAY);
    }
}

constexpr int SCAN_SMEM_BYTES = (2 * 16 * 256 * 2 + 2 * 16 * 16) * 4;  // 67584

// ---------------------------------------------------------------------------
// Kernel 3: output projection. out[m][n] = sum_d g_y[m][d]*Wo[n][d] + bo[n]
// ---------------------------------------------------------------------------
__global__ __launch_bounds__(256) void out_kernel(
    const float* __restrict__ Wo, const float* __restrict__ bo,
    float* __restrict__ out)
{
    __shared__ float As[16][68];
    __shared__ float Bs2[16][68];

    const int m0  = blockIdx.x * 64;
    const int n0  = blockIdx.y * 64;
    const int tid = threadIdx.x;

    const int lrow = tid & 63;
    const int ld4  = (tid >> 6) << 2;
    const int tm   = (tid >> 4) << 2;
    const int tn   = (tid & 15) << 2;

    float acc[4][4];
#pragma unroll
    for (int i = 0; i < 4; ++i)
#pragma unroll
        for (int j = 0; j < 4; ++j) acc[i][j] = 0.0f;

    for (int d0 = 0; d0 < DD; d0 += 16) {
        {
            float4 xa = *(const float4*)(g_y + (size_t)(m0 + lrow) * DD + d0 + ld4);
            As[ld4 + 0][lrow] = xa.x;
            As[ld4 + 1][lrow] = xa.y;
            As[ld4 + 2][lrow] = xa.z;
            As[ld4 + 3][lrow] = xa.w;
        }
        {
            float4 wa = *(const float4*)(Wo + (size_t)(n0 + lrow) * DD + d0 + ld4);
            Bs2[ld4 + 0][lrow] = wa.x;
            Bs2[ld4 + 1][lrow] = wa.y;
            Bs2[ld4 + 2][lrow] = wa.z;
            Bs2[ld4 + 3][lrow] = wa.w;
        }
        __syncthreads();

#pragma unroll
        for (int kk = 0; kk < 16; ++kk) {
            float4 a4 = *(const float4*)&As[kk][tm];
            float4 b4 = *(const float4*)&Bs2[kk][tn];
            float a[4]  = {a4.x, a4.y, a4.z, a4.w};
            float bb[4] = {b4.x, b4.y, b4.z, b4.w};
#pragma unroll
            for (int i = 0; i < 4; ++i)
#pragma unroll
                for (int j = 0; j < 4; ++j)
                    acc[i][j] = fmaf(a[i], bb[j], acc[i][j]);
        }
        __syncthreads();
    }

    float4 bias4 = *(const float4*)(bo + n0 + tn);
    float bb[4] = {bias4.x, bias4.y, bias4.z, bias4.w};
#pragma unroll
    for (int i = 0; i < 4; ++i) {
        float4 r;
        r.x = acc[i][0] + bb[0];
        r.y = acc[i][1] + bb[1];
        r.z = acc[i][2] + bb[2];
        r.w = acc[i][3] + bb[3];
        *(float4*)(out + (size_t)(m0 + tm + i) * DD + n0 + tn) = r;
    }
}

// ---------------------------------------------------------------------------
// Launch: inputs in metadata order:
//   0:x 1:state 2:Wk 3:bk 4:Wv 5:bv 6:Wq 7:bq 8:Wo 9:bo
// Output: out (B*L*D floats) followed by final_state (B*D*D floats).
// ---------------------------------------------------------------------------
extern "C" void kernel_launch(void* const* d_in, const int* in_sizes, int n_in,
                              void* d_out, int out_size)
{
    const float* x     = (const float*)d_in[0];
    const float* state = (const float*)d_in[1];
    const float* Wk    = (const float*)d_in[2];
    const float* bk    = (const float*)d_in[3];
    const float* Wv    = (const float*)d_in[4];
    const float* bv    = (const float*)d_in[5];
    const float* Wq    = (const float*)d_in[6];
    const float* bq    = (const float*)d_in[7];
    const float* Wo    = (const float*)d_in[8];
    const float* bo    = (const float*)d_in[9];

    float* out    = (float*)d_out;
    float* fstate = out + (size_t)MTOT * DD;

    // allow 66KB dynamic SMEM for the scan (host-side attribute, not an alloc;
    // deterministic every call)
    cudaFuncSetAttribute(scan_kernel,
                         cudaFuncAttributeMaxDynamicSharedMemorySize,
                         SCAN_SMEM_BYTES);

    dim3 gemm_grid(MTOT / 64, DD / 64);   // (512, 4)
    qkv_kernel<<<gemm_grid, 256>>>(x, Wk, bk, Wv, bv, Wq, bq);

    dim3 scan_grid(16, BB);               // 128 CTAs: 16 col-groups x 8 batches
    scan_kernel<<<scan_grid, 256, SCAN_SMEM_BYTES>>>(state, fstate);

    out_kernel<<<gemm_grid, 256>>>(Wo, bo, out);
}

// round 8
// speedup vs baseline: 4.5280x; 1.4839x over previous
#include <cuda_runtime.h>
#include <cstdint>

// Problem constants
#define BB    8
#define LSEQ  4096
#define DD    256
#define MTOT  (BB * LSEQ)          // 32768 rows for the projection GEMMs

constexpr float DECAY = 0.9f;
constexpr float LR    = 0.1f;
constexpr int   CS    = 128;               // chunk size S
constexpr int   NCH   = LSEQ / CS;         // 32 chunks per batch
constexpr int   NCHG  = NCH * BB;          // 256 chunk-units total

// Scratch (allocation-free rule: __device__ globals)
__device__ float g_k[MTOT * DD];
__device__ float g_v[MTOT * DD];
__device__ float g_q[MTOT * DD];
__device__ float g_y[MTOT * DD];
__device__ float g_dA[NCHG * DD * DD];     // per-chunk state increments (67MB)
__device__ float g_Ab[NCHG * DD * DD];     // per-chunk A_base checkpoints (67MB)
__device__ float g_P[NCHG * CS * CS];      // per-chunk masked attention (17MB)
__device__ float g_powL[132];              // DECAY^0 .. DECAY^129

// ---------------------------------------------------------------------------
// Kernel 0: build decay power table by serial multiply (matches reference's
// repeated-multiply rounding; deterministic).
// ---------------------------------------------------------------------------
__global__ void pow_kernel() {
    if (threadIdx.x == 0 && blockIdx.x == 0) {
        float p = 1.0f;
        for (int i = 0; i <= 130; ++i) { g_powL[i] = p; p *= DECAY; }
    }
}

// ---------------------------------------------------------------------------
// Kernel 1: fused QKV projection (measured: fp32 FFMA roofline, ~383us).
// ---------------------------------------------------------------------------
__global__ __launch_bounds__(256) void qkv_kernel(
    const float* __restrict__ x,
    const float* __restrict__ Wk, const float* __restrict__ bk,
    const float* __restrict__ Wv, const float* __restrict__ bv,
    const float* __restrict__ Wq, const float* __restrict__ bq)
{
    __shared__ float As[16][68];        // x tile, transposed: As[d][m]
    __shared__ float Bs[3][16][68];     // weight tiles, transposed: Bs[w][d][n]

    const int m0  = blockIdx.x * 64;
    const int n0  = blockIdx.y * 64;
    const int tid = threadIdx.x;

    const int lrow = tid & 63;
    const int ld4  = (tid >> 6) << 2;
    const int tm   = (tid >> 4) << 2;
    const int tn   = (tid & 15) << 2;

    float acc[3][4][4];
#pragma unroll
    for (int w = 0; w < 3; ++w)
#pragma unroll
        for (int i = 0; i < 4; ++i)
#pragma unroll
            for (int j = 0; j < 4; ++j) acc[w][i][j] = 0.0f;

    const float* Ws[3] = {Wk, Wv, Wq};

    for (int d0 = 0; d0 < DD; d0 += 16) {
        {
            float4 xa = *(const float4*)(x + (size_t)(m0 + lrow) * DD + d0 + ld4);
            As[ld4 + 0][lrow] = xa.x;
            As[ld4 + 1][lrow] = xa.y;
            As[ld4 + 2][lrow] = xa.z;
            As[ld4 + 3][lrow] = xa.w;
        }
#pragma unroll
        for (int w = 0; w < 3; ++w) {
            float4 wa = *(const float4*)(Ws[w] + (size_t)(n0 + lrow) * DD + d0 + ld4);
            Bs[w][ld4 + 0][lrow] = wa.x;
            Bs[w][ld4 + 1][lrow] = wa.y;
            Bs[w][ld4 + 2][lrow] = wa.z;
            Bs[w][ld4 + 3][lrow] = wa.w;
        }
        __syncthreads();

#pragma unroll
        for (int kk = 0; kk < 16; ++kk) {
            float4 a4 = *(const float4*)&As[kk][tm];
            float a[4] = {a4.x, a4.y, a4.z, a4.w};
#pragma unroll
            for (int w = 0; w < 3; ++w) {
                float4 b4 = *(const float4*)&Bs[w][kk][tn];
                float bb[4] = {b4.x, b4.y, b4.z, b4.w};
#pragma unroll
                for (int i = 0; i < 4; ++i)
#pragma unroll
                    for (int j = 0; j < 4; ++j)
                        acc[w][i][j] = fmaf(a[i], bb[j], acc[w][i][j]);
            }
        }
        __syncthreads();
    }

    float* outs[3] = {g_k, g_v, g_q};
    const float* biases[3] = {bk, bv, bq};
#pragma unroll
    for (int w = 0; w < 3; ++w) {
        float4 bias4 = *(const float4*)(biases[w] + n0 + tn);
        float bb[4] = {bias4.x, bias4.y, bias4.z, bias4.w};
#pragma unroll
        for (int i = 0; i < 4; ++i) {
            float4 r;
            r.x = acc[w][i][0] + bb[0];
            r.y = acc[w][i][1] + bb[1];
            r.z = acc[w][i][2] + bb[2];
            r.w = acc[w][i][3] + bb[3];
            *(float4*)(outs[w] + (size_t)(m0 + tm + i) * DD + n0 + tn) = r;
        }
    }
}

// ---------------------------------------------------------------------------
// Kernel 2: per-chunk state increment.
//   dA[g][i][j] = sum_{u<CS} (eta * lambda^{CS-1-u} * k[t0+u][i]) * v[t0+u][j]
// Grid (4,4,NCHG): 64x64 tile of the DxD output per CTA, contract over u.
// ---------------------------------------------------------------------------
__global__ __launch_bounds__(256) void dA_kernel()
{
    __shared__ float Ks[16][68];   // Ks[u][i], scale folded
    __shared__ float Vs[16][68];   // Vs[u][j]

    const int g   = blockIdx.z;            // chunk-unit: b*NCH + c
    const int b   = g >> 5;
    const int c   = g & 31;
    const int i0  = blockIdx.x * 64;
    const int j0  = blockIdx.y * 64;
    const int tid = threadIdx.x;
    const int t0  = c * CS;

    const float* kg = g_k + (size_t)b * LSEQ * DD + (size_t)t0 * DD;
    const float* vg = g_v + (size_t)b * LSEQ * DD + (size_t)t0 * DD;

    const int srow = tid >> 4;             // staging: u within 16-slice
    const int sc4  = (tid & 15) << 2;      // staging: 4-col group
    const int tm   = (tid >> 4) << 2;      // compute: i group
    const int tn   = (tid & 15) << 2;      // compute: j group

    float acc[4][4];
#pragma unroll
    for (int i = 0; i < 4; ++i)
#pragma unroll
        for (int j = 0; j < 4; ++j) acc[i][j] = 0.0f;

    for (int u0 = 0; u0 < CS; u0 += 16) {
        const int u = u0 + srow;
        const float ksc = LR * g_powL[CS - 1 - u];
        {
            float4 ka = *(const float4*)(kg + (size_t)u * DD + i0 + sc4);
            Ks[srow][sc4 + 0] = ka.x * ksc;
            Ks[srow][sc4 + 1] = ka.y * ksc;
            Ks[srow][sc4 + 2] = ka.z * ksc;
            Ks[srow][sc4 + 3] = ka.w * ksc;
            float4 va = *(const float4*)(vg + (size_t)u * DD + j0 + sc4);
            *(float4*)&Vs[srow][sc4] = va;
        }
        __syncthreads();

#pragma unroll
        for (int uu = 0; uu < 16; ++uu) {
            float4 a4 = *(const float4*)&Ks[uu][tm];
            float4 b4 = *(const float4*)&Vs[uu][tn];
            float a[4]  = {a4.x, a4.y, a4.z, a4.w};
            float bb[4] = {b4.x, b4.y, b4.z, b4.w};
#pragma unroll
            for (int i = 0; i < 4; ++i)
#pragma unroll
                for (int j = 0; j < 4; ++j)
                    acc[i][j] = fmaf(a[i], bb[j], acc[i][j]);
        }
        __syncthreads();
    }

    float* dst = g_dA + (size_t)g * DD * DD;
#pragma unroll
    for (int i = 0; i < 4; ++i)
        *(float4*)(dst + (size_t)(i0 + tm + i) * DD + j0 + tn) =
            make_float4(acc[i][0], acc[i][1], acc[i][2], acc[i][3]);
}

// ---------------------------------------------------------------------------
// Kernel 3: serial prefix over chunks (element-parallel).
//   Ab[c] = A_base before chunk c;  a_{c+1} = lambda^CS * a_c + dA[c]
// Grid (16, BB), 256 threads; each thread owns 16 contiguous state elements.
// ---------------------------------------------------------------------------
__global__ __launch_bounds__(256) void prefix_kernel(
    const float* __restrict__ state, float* __restrict__ fstate)
{
    const int b  = blockIdx.y;
    const int e0 = (blockIdx.x * 256 + threadIdx.x) * 16;   // within D*D
    const float lamS = g_powL[CS];

    float4 a[4];
#pragma unroll
    for (int i = 0; i < 4; ++i)
        a[i] = *(const float4*)(state + (size_t)b * DD * DD + e0 + i * 4);

    for (int c = 0; c < NCH; ++c) {
        float* ab = g_Ab + ((size_t)(b * NCH + c)) * DD * DD + e0;
        const float* da = g_dA + ((size_t)(b * NCH + c)) * DD * DD + e0;
#pragma unroll
        for (int i = 0; i < 4; ++i) {
            *(float4*)(ab + i * 4) = a[i];
            float4 d = *(const float4*)(da + i * 4);
            a[i].x = fmaf(lamS, a[i].x, d.x);
            a[i].y = fmaf(lamS, a[i].y, d.y);
            a[i].z = fmaf(lamS, a[i].z, d.z);
            a[i].w = fmaf(lamS, a[i].w, d.w);
        }
    }
#pragma unroll
    for (int i = 0; i < 4; ++i)
        *(float4*)(fstate + (size_t)b * DD * DD + e0 + i * 4) = a[i];
}

// ---------------------------------------------------------------------------
// Kernel 4: intra-chunk attention matrix.
//   P[g][s][u] = (u<=s) ? eta * lambda^(s-u) * dot(q_s, k_u) : 0
// Grid (2,2,NCHG): 64x64 tile of the CSxCS output, contract over d (256).
// ---------------------------------------------------------------------------
__global__ __launch_bounds__(256) void p_kernel()
{
    __shared__ float Qs[16][68];   // Qs[d][s]
    __shared__ float Ks[16][68];   // Ks[d][u]

    const int g   = blockIdx.z;
    const int b   = g >> 5;
    const int c   = g & 31;
    const int s0  = blockIdx.x * 64;
    const int u0  = blockIdx.y * 64;
    const int tid = threadIdx.x;
    const int t0  = c * CS;

    const float* qg = g_q + (size_t)b * LSEQ * DD + (size_t)t0 * DD;
    const float* kg = g_k + (size_t)b * LSEQ * DD + (size_t)t0 * DD;

    const int lrow = tid & 63;
    const int ld4  = (tid >> 6) << 2;
    const int tm   = (tid >> 4) << 2;   // s group
    const int tn   = (tid & 15) << 2;   // u group

    float acc[4][4];
#pragma unroll
    for (int i = 0; i < 4; ++i)
#pragma unroll
        for (int j = 0; j < 4; ++j) acc[i][j] = 0.0f;

    for (int d0 = 0; d0 < DD; d0 += 16) {
        {
            float4 qa = *(const float4*)(qg + (size_t)(s0 + lrow) * DD + d0 + ld4);
            Qs[ld4 + 0][lrow] = qa.x;
            Qs[ld4 + 1][lrow] = qa.y;
            Qs[ld4 + 2][lrow] = qa.z;
            Qs[ld4 + 3][lrow] = qa.w;
            float4 ka = *(const float4*)(kg + (size_t)(u0 + lrow) * DD + d0 + ld4);
            Ks[ld4 + 0][lrow] = ka.x;
            Ks[ld4 + 1][lrow] = ka.y;
            Ks[ld4 + 2][lrow] = ka.z;
            Ks[ld4 + 3][lrow] = ka.w;
        }
        __syncthreads();

#pragma unroll
        for (int dd = 0; dd < 16; ++dd) {
            float4 a4 = *(const float4*)&Qs[dd][tm];
            float4 b4 = *(const float4*)&Ks[dd][tn];
            float a[4]  = {a4.x, a4.y, a4.z, a4.w};
            float bb[4] = {b4.x, b4.y, b4.z, b4.w};
#pragma unroll
            for (int i = 0; i < 4; ++i)
#pragma unroll
                for (int j = 0; j < 4; ++j)
                    acc[i][j] = fmaf(a[i], bb[j], acc[i][j]);
        }
        __syncthreads();
    }

    float* dst = g_P + (size_t)g * CS * CS;
#pragma unroll
    for (int i = 0; i < 4; ++i) {
        const int s = s0 + tm + i;
        float4 r;
        float* rr = &r.x;
#pragma unroll
        for (int j = 0; j < 4; ++j) {
            const int u = u0 + tn + j;
            rr[j] = (u <= s) ? acc[i][j] * LR * g_powL[s - u] : 0.0f;
        }
        *(float4*)(dst + (size_t)s * CS + u0 + tn) = r;
    }
}

// ---------------------------------------------------------------------------
// Kernel 5: chunk output.
//   Y[s][j] = sum_{u<CS} P[s][u]*V[u][j] + lambda^(s+1) * sum_d Q[s][d]*Ab[d][j]
// Grid (2,4,NCHG): 64x64 tile of the CSxDD output.
// ---------------------------------------------------------------------------
__global__ __launch_bounds__(256) void y_kernel()
{
    __shared__ float Sa[16][68];
    __shared__ float Sb[16][68];

    const int g   = blockIdx.z;
    const int b   = g >> 5;
    const int c   = g & 31;
    const int s0  = blockIdx.x * 64;
    const int j0  = blockIdx.y * 64;
    const int tid = threadIdx.x;
    const int t0  = c * CS;

    const float* pg = g_P + (size_t)g * CS * CS;
    const float* vg = g_v + (size_t)b * LSEQ * DD + (size_t)t0 * DD;
    const float* qg = g_q + (size_t)b * LSEQ * DD + (size_t)t0 * DD;
    const float* ab = g_Ab + (size_t)g * DD * DD;

    const int lrow = tid & 63;
    const int ld4  = (tid >> 6) << 2;
    const int srow = tid >> 4;
    const int sc4  = (tid & 15) << 2;
    const int tm   = (tid >> 4) << 2;
    const int tn   = (tid & 15) << 2;

    float acc[4][4];
#pragma unroll
    for (int i = 0; i < 4; ++i)
#pragma unroll
        for (int j = 0; j < 4; ++j) acc[i][j] = 0.0f;

    // Phase 1: P (transposed stage) x V, contract u over CS=128
    for (int u0 = 0; u0 < CS; u0 += 16) {
        {
            float4 pa = *(const float4*)(pg + (size_t)(s0 + lrow) * CS + u0 + ld4);
            Sa[ld4 + 0][lrow] = pa.x;
            Sa[ld4 + 1][lrow] = pa.y;
            Sa[ld4 + 2][lrow] = pa.z;
            Sa[ld4 + 3][lrow] = pa.w;
            float4 va = *(const float4*)(vg + (size_t)(u0 + srow) * DD + j0 + sc4);
            *(float4*)&Sb[srow][sc4] = va;
        }
        __syncthreads();

#pragma unroll
        for (int uu = 0; uu < 16; ++uu) {
            float4 a4 = *(const float4*)&Sa[uu][tm];
            float4 b4 = *(const float4*)&Sb[uu][tn];
            float a[4]  = {a4.x, a4.y, a4.z, a4.w};
            float bb[4] = {b4.x, b4.y, b4.z, b4.w};
#pragma unroll
            for (int i = 0; i < 4; ++i)
#pragma unroll
                for (int j = 0; j < 4; ++j)
                    acc[i][j] = fmaf(a[i], bb[j], acc[i][j]);
        }
        __syncthreads();
    }

    // Phase 2: (lambda^(s+1) Q) (transposed stage) x A_base, contract d over 256
    for (int d0 = 0; d0 < DD; d0 += 16) {
        {
            const float qsc = g_powL[s0 + lrow + 1];
            float4 qa = *(const float4*)(qg + (size_t)(s0 + lrow) * DD + d0 + ld4);
            Sa[ld4 + 0][lrow] = qa.x * qsc;
            Sa[ld4 + 1][lrow] = qa.y * qsc;
            Sa[ld4 + 2][lrow] = qa.z * qsc;
            Sa[ld4 + 3][lrow] = qa.w * qsc;
            float4 aa = *(const float4*)(ab + (size_t)(d0 + srow) * DD + j0 + sc4);
            *(float4*)&Sb[srow][sc4] = aa;
        }
        __syncthreads();

#pragma unroll
        for (int dd = 0; dd < 16; ++dd) {
            float4 a4 = *(const float4*)&Sa[dd][tm];
            float4 b4 = *(const float4*)&Sb[dd][tn];
            float a[4]  = {a4.x, a4.y, a4.z, a4.w};
            float bb[4] = {b4.x, b4.y, b4.z, b4.w};
#pragma unroll
            for (int i = 0; i < 4; ++i)
#pragma unroll
                for (int j = 0; j < 4; ++j)
                    acc[i][j] = fmaf(a[i], bb[j], acc[i][j]);
        }
        __syncthreads();
    }

    float* dst = g_y + (size_t)b * LSEQ * DD + (size_t)t0 * DD;
#pragma unroll
    for (int i = 0; i < 4; ++i)
        *(float4*)(dst + (size_t)(s0 + tm + i) * DD + j0 + tn) =
            make_float4(acc[i][0], acc[i][1], acc[i][2], acc[i][3]);
}

// ---------------------------------------------------------------------------
// Kernel 6: output projection. out[m][n] = sum_d g_y[m][d]*Wo[n][d] + bo[n]
// ---------------------------------------------------------------------------
__global__ __launch_bounds__(256) void out_kernel(
    const float* __restrict__ Wo, const float* __restrict__ bo,
    float* __restrict__ out)
{
    __shared__ float As[16][68];
    __shared__ float Bs2[16][68];

    const int m0  = blockIdx.x * 64;
    const int n0  = blockIdx.y * 64;
    const int tid = threadIdx.x;

    const int lrow = tid & 63;
    const int ld4  = (tid >> 6) << 2;
    const int tm   = (tid >> 4) << 2;
    const int tn   = (tid & 15) << 2;

    float acc[4][4];
#pragma unroll
    for (int i = 0; i < 4; ++i)
#pragma unroll
        for (int j = 0; j < 4; ++j) acc[i][j] = 0.0f;

    for (int d0 = 0; d0 < DD; d0 += 16) {
        {
            float4 xa = *(const float4*)(g_y + (size_t)(m0 + lrow) * DD + d0 + ld4);
            As[ld4 + 0][lrow] = xa.x;
            As[ld4 + 1][lrow] = xa.y;
            As[ld4 + 2][lrow] = xa.z;
            As[ld4 + 3][lrow] = xa.w;
        }
        {
            float4 wa = *(const float4*)(Wo + (size_t)(n0 + lrow) * DD + d0 + ld4);
            Bs2[ld4 + 0][lrow] = wa.x;
            Bs2[ld4 + 1][lrow] = wa.y;
            Bs2[ld4 + 2][lrow] = wa.z;
            Bs2[ld4 + 3][lrow] = wa.w;
        }
        __syncthreads();

#pragma unroll
        for (int kk = 0; kk < 16; ++kk) {
            float4 a4 = *(const float4*)&As[kk][tm];
            float4 b4 = *(const float4*)&Bs2[kk][tn];
            float a[4]  = {a4.x, a4.y, a4.z, a4.w};
            float bb[4] = {b4.x, b4.y, b4.z, b4.w};
#pragma unroll
            for (int i = 0; i < 4; ++i)
#pragma unroll
                for (int j = 0; j < 4; ++j)
                    acc[i][j] = fmaf(a[i], bb[j], acc[i][j]);
        }
        __syncthreads();
    }

    float4 bias4 = *(const float4*)(bo + n0 + tn);
    float bb[4] = {bias4.x, bias4.y, bias4.z, bias4.w};
#pragma unroll
    for (int i = 0; i < 4; ++i) {
        float4 r;
        r.x = acc[i][0] + bb[0];
        r.y = acc[i][1] + bb[1];
        r.z = acc[i][2] + bb[2];
        r.w = acc[i][3] + bb[3];
        *(float4*)(out + (size_t)(m0 + tm + i) * DD + n0 + tn) = r;
    }
}

// ---------------------------------------------------------------------------
// Launch. Inputs: 0:x 1:state 2:Wk 3:bk 4:Wv 5:bv 6:Wq 7:bq 8:Wo 9:bo
// Output: out (B*L*D floats) followed by final_state (B*D*D floats).
// ---------------------------------------------------------------------------
extern "C" void kernel_launch(void* const* d_in, const int* in_sizes, int n_in,
                              void* d_out, int out_size)
{
    const float* x     = (const float*)d_in[0];
    const float* state = (const float*)d_in[1];
    const float* Wk    = (const float*)d_in[2];
    const float* bk    = (const float*)d_in[3];
    const float* Wv    = (const float*)d_in[4];
    const float* bv    = (const float*)d_in[5];
    const float* Wq    = (const float*)d_in[6];
    const float* bq    = (const float*)d_in[7];
    const float* Wo    = (const float*)d_in[8];
    const float* bo    = (const float*)d_in[9];

    float* out    = (float*)d_out;
    float* fstate = out + (size_t)MTOT * DD;

    pow_kernel<<<1, 32>>>();

    dim3 gemm_grid(MTOT / 64, DD / 64);           // (512, 4)
    qkv_kernel<<<gemm_grid, 256>>>(x, Wk, bk, Wv, bv, Wq, bq);

    dA_kernel<<<dim3(4, 4, NCHG), 256>>>();       // per-chunk K'^T V

    prefix_kernel<<<dim3(16, BB), 256>>>(state, fstate);

    p_kernel<<<dim3(2, 2, NCHG), 256>>>();        // masked decay QK^T

    y_kernel<<<dim3(2, 4, NCHG), 256>>>();        // P V + (lam^(s+1) Q) A_base

    out_kernel<<<gemm_grid, 256>>>(Wo, bo, out);
}

// round 12
// speedup vs baseline: 6.0676x; 1.3400x over previous
#include <cuda_runtime.h>
#include <cuda_bf16.h>
#include <cstdint>

// Problem constants
#define BB    8
#define LSEQ  4096
#define DD    256
#define MTOT  (BB * LSEQ)          // 32768 rows for the projection GEMMs

constexpr float DECAY = 0.9f;
constexpr float LR    = 0.1f;
constexpr int   CS    = 128;               // chunk size S
constexpr int   NCH   = LSEQ / CS;         // 32 chunks per batch
constexpr int   NCHG  = NCH * BB;          // 256 chunk-units total

// Scratch (allocation-free rule: __device__ globals).
// NOTE: these may ONLY be referenced from device code. Passing them as kernel
// arguments from host code yields a bogus host-context symbol address and a
// faulting kernel (R11 failure mode).
__device__ float g_k[MTOT * DD];
__device__ float g_v[MTOT * DD];
__device__ float g_q[MTOT * DD];
__device__ float g_y[MTOT * DD];
__device__ float g_dA[NCHG * DD * DD];     // per-chunk state increments
__device__ float g_Ab[NCHG * DD * DD];     // per-chunk A_base checkpoints
__device__ float g_P[NCHG * CS * CS];      // per-chunk masked attention
__device__ float g_powL[132];              // DECAY^0 .. DECAY^129

// ===========================================================================
// mma.sync helpers (plain sm_80+ PTX; compiles under compute_103 — no 'a'
// arch-features, unlike tcgen05 which ptxas rejected for target sm_103)
// ===========================================================================
__device__ __forceinline__ void ldmx4(uint32_t& r0, uint32_t& r1,
                                      uint32_t& r2, uint32_t& r3, uint32_t addr)
{
    asm volatile("ldmatrix.sync.aligned.m8n8.x4.shared.b16 {%0,%1,%2,%3}, [%4];"
                 : "=r"(r0), "=r"(r1), "=r"(r2), "=r"(r3) : "r"(addr));
}
__device__ __forceinline__ void mma16816(float* c, const uint32_t* a,
                                         const uint32_t* b)
{
    asm volatile(
        "mma.sync.aligned.m16n8k16.row.col.f32.bf16.bf16.f32 "
        "{%0,%1,%2,%3}, {%4,%5,%6,%7}, {%8,%9}, {%0,%1,%2,%3};"
        : "+f"(c[0]), "+f"(c[1]), "+f"(c[2]), "+f"(c[3])
        : "r"(a[0]), "r"(a[1]), "r"(a[2]), "r"(a[3]), "r"(b[0]), "r"(b[1]));
}
__device__ __forceinline__ uint32_t smem_to_u32(const void* p) {
    uint32_t a;
    asm("{ .reg .u64 t; cvta.to.shared.u64 t, %1; cvt.u32.u64 %0, t; }"
        : "=r"(a) : "l"(p));
    return a;
}

// split fp32 -> (hi bf16, lo bf16) pairs, 8 at a time, packed 2-per-u32
__device__ __forceinline__ void split8(const float* __restrict__ g,
                                       uint4& hi, uint4& lo)
{
    float4 f0 = *(const float4*)g;
    float4 f1 = *(const float4*)(g + 4);
    float f[8] = {f0.x, f0.y, f0.z, f0.w, f1.x, f1.y, f1.z, f1.w};
    unsigned short hs[8], ls[8];
#pragma unroll
    for (int i = 0; i < 8; ++i) {
        __nv_bfloat16 h = __float2bfloat16_rn(f[i]);
        hs[i] = __bfloat16_as_ushort(h);
        float r = f[i] - __bfloat162float(h);
        ls[i] = __bfloat16_as_ushort(__float2bfloat16_rn(r));
    }
    hi.x = (uint32_t)hs[0] | ((uint32_t)hs[1] << 16);
    hi.y = (uint32_t)hs[2] | ((uint32_t)hs[3] << 16);
    hi.z = (uint32_t)hs[4] | ((uint32_t)hs[5] << 16);
    hi.w = (uint32_t)hs[6] | ((uint32_t)hs[7] << 16);
    lo.x = (uint32_t)ls[0] | ((uint32_t)ls[1] << 16);
    lo.y = (uint32_t)ls[2] | ((uint32_t)ls[3] << 16);
    lo.z = (uint32_t)ls[4] | ((uint32_t)ls[5] << 16);
    lo.w = (uint32_t)ls[6] | ((uint32_t)ls[7] << 16);
}

// ===========================================================================
// Kernel 0: decay power table (serial multiply, matches reference rounding)
// ===========================================================================
__global__ void pow_kernel() {
    if (threadIdx.x == 0 && blockIdx.x == 0) {
        float p = 1.0f;
        for (int i = 0; i <= 130; ++i) { g_powL[i] = p; p *= DECAY; }
    }
}

// ===========================================================================
// mma_gemm: C[m][n] = sum_d A[m][d] * W[n][d] + bias[n]
// dst_sel: 0->C=g_k, 1->C=g_v, 2->C=g_q (A = A_ext);  3->C=C_ext, A=g_y.
// (device globals must be bound INSIDE the kernel, not passed from host)
// CTA tile 128x128, 8 warps (2M x 4N), warp tile 64x32 (4 m-frags x 4 n-frags).
// K = 256 in 4 slices of 64; bf16 2-term split, 3 passes (hh + hl + lh).
// SMEM rows padded to 72 halves (144B): conflict-free ldmatrix, 16B-aligned.
// ===========================================================================
constexpr int ROWB    = 144;        // bytes per staged smem row (72 halves)
constexpr int TB_AHI  = 0;
constexpr int TB_ALO  = 18432;      // 128*144
constexpr int TB_WHI  = 36864;
constexpr int TB_WLO  = 55296;
constexpr int TB_SMEM = 73728;

__global__ __launch_bounds__(256) void mma_gemm(
    const float* __restrict__ A_ext,   // [M, 256] row-major (used if dst_sel<3)
    const float* __restrict__ W,       // [256, 256] row-major
    const float* __restrict__ bias,    // [256]
    float* __restrict__ C_ext,         // [M, 256] (used if dst_sel==3)
    int dst_sel)
{
    extern __shared__ char sm[];
    const uint32_t sb = smem_to_u32(sm);
    const int tid  = threadIdx.x;
    const int wid  = tid >> 5;
    const int lane = tid & 31;
    const size_t m0 = (size_t)blockIdx.x * 128;
    const int    n0 = blockIdx.y * 128;
    const int warpM = wid >> 2;          // 0..1
    const int warpN = wid & 3;           // 0..3

    // bind device-global scratch in device code (legal symbol reference)
    const float* A = (dst_sel == 3) ? g_y : A_ext;
    float* C;
    switch (dst_sel) {
        case 0:  C = g_k;   break;
        case 1:  C = g_v;   break;
        case 2:  C = g_q;   break;
        default: C = C_ext; break;
    }

    float acc[4][4][4];
#pragma unroll
    for (int mf = 0; mf < 4; ++mf)
#pragma unroll
        for (int nf = 0; nf < 4; ++nf)
#pragma unroll
            for (int i = 0; i < 4; ++i) acc[mf][nf][i] = 0.0f;

    // ldmatrix lane address components (constant across slices)
    const int arow  = warpM * 64 + (lane & 15);       // + mf*16
    const int acolh = (lane >> 4) * 8;                // halves within k16
    const int brow  = warpN * 32 + ((lane >> 4) << 3) + (lane & 7);  // + p*16
    const int bcolh = (lane & 8);                     // 0 or 8 halves

    for (int ks = 0; ks < 4; ++ks) {
        const int k0 = ks * 64;
        // ---- stage slice: fp32 -> split bf16 hi/lo, 4 chunks of 8 per thread
#pragma unroll
        for (int c = 0; c < 4; ++c) {
            const int ci  = tid + c * 256;            // 0..1023
            const int row = ci >> 3;                  // 0..127
            const int c8  = ci & 7;
            uint4 hi, lo;
            split8(A + (m0 + row) * DD + k0 + c8 * 8, hi, lo);
            *(uint4*)(sm + TB_AHI + row * ROWB + c8 * 16) = hi;
            *(uint4*)(sm + TB_ALO + row * ROWB + c8 * 16) = lo;
            split8(W + (size_t)(n0 + row) * DD + k0 + c8 * 8, hi, lo);
            *(uint4*)(sm + TB_WHI + row * ROWB + c8 * 16) = hi;
            *(uint4*)(sm + TB_WLO + row * ROWB + c8 * 16) = lo;
        }
        __syncthreads();

        const uint32_t abufs[3] = {sb + TB_AHI, sb + TB_AHI, sb + TB_ALO};
        const uint32_t bbufs[3] = {sb + TB_WHI, sb + TB_WLO, sb + TB_WHI};
#pragma unroll
        for (int pass = 0; pass < 3; ++pass) {
            const uint32_t ab = abufs[pass];
            const uint32_t bb = bbufs[pass];
#pragma unroll
            for (int k16 = 0; k16 < 4; ++k16) {
                uint32_t af[4][4];
#pragma unroll
                for (int mf = 0; mf < 4; ++mf) {
                    const uint32_t addr =
                        ab + (uint32_t)(arow + mf * 16) * ROWB +
                        (uint32_t)(k16 * 16 + acolh) * 2;
                    ldmx4(af[mf][0], af[mf][1], af[mf][2], af[mf][3], addr);
                }
                uint32_t bf[4][2];
#pragma unroll
                for (int p = 0; p < 2; ++p) {
                    const uint32_t addr =
                        bb + (uint32_t)(brow + p * 16) * ROWB +
                        (uint32_t)(k16 * 16 + bcolh) * 2;
                    uint32_t r0, r1, r2, r3;
                    ldmx4(r0, r1, r2, r3, addr);
                    bf[2 * p][0]     = r0;  bf[2 * p][1]     = r1;
                    bf[2 * p + 1][0] = r2;  bf[2 * p + 1][1] = r3;
                }
#pragma unroll
                for (int mf = 0; mf < 4; ++mf)
#pragma unroll
                    for (int nf = 0; nf < 4; ++nf)
                        mma16816(acc[mf][nf], af[mf], bf[nf]);
            }
        }
        __syncthreads();
    }

    // ---- epilogue: c0,c1 -> (row, col..col+1); c2,c3 -> row+8
    const int gid = lane >> 2;
    const int tig = lane & 3;
#pragma unroll
    for (int mf = 0; mf < 4; ++mf) {
        const size_t r0 = m0 + warpM * 64 + mf * 16 + gid;
#pragma unroll
        for (int nf = 0; nf < 4; ++nf) {
            const int cb = n0 + warpN * 32 + nf * 8 + tig * 2;
            const float b0 = __ldg(bias + cb);
            const float b1 = __ldg(bias + cb + 1);
            *(float2*)(C + r0 * DD + cb) =
                make_float2(acc[mf][nf][0] + b0, acc[mf][nf][1] + b1);
            *(float2*)(C + (r0 + 8) * DD + cb) =
                make_float2(acc[mf][nf][2] + b0, acc[mf][nf][3] + b1);
        }
    }
}

// ===========================================================================
// Kernel 2: per-chunk state increment (fp32; mma conversion after core proven)
//   dA[g][i][j] = sum_{u<CS} (eta * lambda^{CS-1-u} * k[t0+u][i]) * v[t0+u][j]
// ===========================================================================
__global__ __launch_bounds__(256) void dA_kernel()
{
    __shared__ float Ks[16][68];
    __shared__ float Vs[16][68];

    const int g   = blockIdx.z;
    const int b   = g >> 5;
    const int c   = g & 31;
    const int i0  = blockIdx.x * 64;
    const int j0  = blockIdx.y * 64;
    const int tid = threadIdx.x;
    const int t0  = c * CS;

    const float* kg = g_k + (size_t)b * LSEQ * DD + (size_t)t0 * DD;
    const float* vg = g_v + (size_t)b * LSEQ * DD + (size_t)t0 * DD;

    const int srow = tid >> 4;
    const int sc4  = (tid & 15) << 2;
    const int tm   = (tid >> 4) << 2;
    const int tn   = (tid & 15) << 2;

    float acc[4][4];
#pragma unroll
    for (int i = 0; i < 4; ++i)
#pragma unroll
        for (int j = 0; j < 4; ++j) acc[i][j] = 0.0f;

    for (int u0 = 0; u0 < CS; u0 += 16) {
        const int u = u0 + srow;
        const float ksc = LR * g_powL[CS - 1 - u];
        {
            float4 ka = *(const float4*)(kg + (size_t)u * DD + i0 + sc4);
            Ks[srow][sc4 + 0] = ka.x * ksc;
            Ks[srow][sc4 + 1] = ka.y * ksc;
            Ks[srow][sc4 + 2] = ka.z * ksc;
            Ks[srow][sc4 + 3] = ka.w * ksc;
            float4 va = *(const float4*)(vg + (size_t)u * DD + j0 + sc4);
            *(float4*)&Vs[srow][sc4] = va;
        }
        __syncthreads();

#pragma unroll
        for (int uu = 0; uu < 16; ++uu) {
            float4 a4 = *(const float4*)&Ks[uu][tm];
            float4 b4 = *(const float4*)&Vs[uu][tn];
            float a[4]  = {a4.x, a4.y, a4.z, a4.w};
            float bb[4] = {b4.x, b4.y, b4.z, b4.w};
#pragma unroll
            for (int i = 0; i < 4; ++i)
#pragma unroll
                for (int j = 0; j < 4; ++j)
                    acc[i][j] = fmaf(a[i], bb[j], acc[i][j]);
        }
        __syncthreads();
    }

    float* dst = g_dA + (size_t)g * DD * DD;
#pragma unroll
    for (int i = 0; i < 4; ++i)
        *(float4*)(dst + (size_t)(i0 + tm + i) * DD + j0 + tn) =
            make_float4(acc[i][0], acc[i][1], acc[i][2], acc[i][3]);
}

// ===========================================================================
// Kernel 3: serial prefix over chunks (element-parallel, DRAM-bound, 32us).
// ===========================================================================
__global__ __launch_bounds__(256) void prefix_kernel(
    const float* __restrict__ state, float* __restrict__ fstate)
{
    const int b  = blockIdx.y;
    const int e0 = (blockIdx.x * 256 + threadIdx.x) * 16;
    const float lamS = g_powL[CS];

    float4 a[4];
#pragma unroll
    for (int i = 0; i < 4; ++i)
        a[i] = *(const float4*)(state + (size_t)b * DD * DD + e0 + i * 4);

    for (int c = 0; c < NCH; ++c) {
        float* ab = g_Ab + ((size_t)(b * NCH + c)) * DD * DD + e0;
        const float* da = g_dA + ((size_t)(b * NCH + c)) * DD * DD + e0;
#pragma unroll
        for (int i = 0; i < 4; ++i) {
            *(float4*)(ab + i * 4) = a[i];
            float4 d = *(const float4*)(da + i * 4);
            a[i].x = fmaf(lamS, a[i].x, d.x);
            a[i].y = fmaf(lamS, a[i].y, d.y);
            a[i].z = fmaf(lamS, a[i].z, d.z);
            a[i].w = fmaf(lamS, a[i].w, d.w);
        }
    }
#pragma unroll
    for (int i = 0; i < 4; ++i)
        *(float4*)(fstate + (size_t)b * DD * DD + e0 + i * 4) = a[i];
}

// ===========================================================================
// Kernel 4: intra-chunk attention matrix (fp32).
//   P[g][s][u] = (u<=s) ? eta * lambda^(s-u) * dot(q_s, k_u) : 0
// ===========================================================================
__global__ __launch_bounds__(256) void p_kernel()
{
    __shared__ float Qs[16][68];
    __shared__ float Ks[16][68];

    const int g   = blockIdx.z;
    const int b   = g >> 5;
    const int c   = g & 31;
    const int s0  = blockIdx.x * 64;
    const int u0  = blockIdx.y * 64;
    const int tid = threadIdx.x;
    const int t0  = c * CS;

    const float* qg = g_q + (size_t)b * LSEQ * DD + (size_t)t0 * DD;
    const float* kg = g_k + (size_t)b * LSEQ * DD + (size_t)t0 * DD;

    const int lrow = tid & 63;
    const int ld4  = (tid >> 6) << 2;
    const int tm   = (tid >> 4) << 2;
    const int tn   = (tid & 15) << 2;

    float acc[4][4];
#pragma unroll
    for (int i = 0; i < 4; ++i)
#pragma unroll
        for (int j = 0; j < 4; ++j) acc[i][j] = 0.0f;

    for (int d0 = 0; d0 < DD; d0 += 16) {
        {
            float4 qa = *(const float4*)(qg + (size_t)(s0 + lrow) * DD + d0 + ld4);
            Qs[ld4 + 0][lrow] = qa.x;
            Qs[ld4 + 1][lrow] = qa.y;
            Qs[ld4 + 2][lrow] = qa.z;
            Qs[ld4 + 3][lrow] = qa.w;
            float4 ka = *(const float4*)(kg + (size_t)(u0 + lrow) * DD + d0 + ld4);
            Ks[ld4 + 0][lrow] = ka.x;
            Ks[ld4 + 1][lrow] = ka.y;
            Ks[ld4 + 2][lrow] = ka.z;
            Ks[ld4 + 3][lrow] = ka.w;
        }
        __syncthreads();

#pragma unroll
        for (int dd = 0; dd < 16; ++dd) {
            float4 a4 = *(const float4*)&Qs[dd][tm];
            float4 b4 = *(const float4*)&Ks[dd][tn];
            float a[4]  = {a4.x, a4.y, a4.z, a4.w};
            float bb[4] = {b4.x, b4.y, b4.z, b4.w};
#pragma unroll
            for (int i = 0; i < 4; ++i)
#pragma unroll
                for (int j = 0; j < 4; ++j)
                    acc[i][j] = fmaf(a[i], bb[j], acc[i][j]);
        }
        __syncthreads();
    }

    float* dst = g_P + (size_t)g * CS * CS;
#pragma unroll
    for (int i = 0; i < 4; ++i) {
        const int s = s0 + tm + i;
        float4 r;
        float* rr = &r.x;
#pragma unroll
        for (int j = 0; j < 4; ++j) {
            const int u = u0 + tn + j;
            rr[j] = (u <= s) ? acc[i][j] * LR * g_powL[s - u] : 0.0f;
        }
        *(float4*)(dst + (size_t)s * CS + u0 + tn) = r;
    }
}

// ===========================================================================
// Kernel 5: chunk output (fp32).
//   Y[s][j] = sum_u P[s][u]*V[u][j] + lambda^(s+1) * sum_d Q[s][d]*Ab[d][j]
// ===========================================================================
__global__ __launch_bounds__(256) void y_kernel()
{
    __shared__ float Sa[16][68];
    __shared__ float Sb[16][68];

    const int g   = blockIdx.z;
    const int b   = g >> 5;
    const int c   = g & 31;
    const int s0  = blockIdx.x * 64;
    const int j0  = blockIdx.y * 64;
    const int tid = threadIdx.x;
    const int t0  = c * CS;

    const float* pg = g_P + (size_t)g * CS * CS;
    const float* vg = g_v + (size_t)b * LSEQ * DD + (size_t)t0 * DD;
    const float* qg = g_q + (size_t)b * LSEQ * DD + (size_t)t0 * DD;
    const float* ab = g_Ab + (size_t)g * DD * DD;

    const int lrow = tid & 63;
    const int ld4  = (tid >> 6) << 2;
    const int srow = tid >> 4;
    const int sc4  = (tid & 15) << 2;
    const int tm   = (tid >> 4) << 2;
    const int tn   = (tid & 15) << 2;

    float acc[4][4];
#pragma unroll
    for (int i = 0; i < 4; ++i)
#pragma unroll
        for (int j = 0; j < 4; ++j) acc[i][j] = 0.0f;

    for (int u0 = 0; u0 < CS; u0 += 16) {
        {
            float4 pa = *(const float4*)(pg + (size_t)(s0 + lrow) * CS + u0 + ld4);
            Sa[ld4 + 0][lrow] = pa.x;
            Sa[ld4 + 1][lrow] = pa.y;
            Sa[ld4 + 2][lrow] = pa.z;
            Sa[ld4 + 3][lrow] = pa.w;
            float4 va = *(const float4*)(vg + (size_t)(u0 + srow) * DD + j0 + sc4);
            *(float4*)&Sb[srow][sc4] = va;
        }
        __syncthreads();

#pragma unroll
        for (int uu = 0; uu < 16; ++uu) {
            float4 a4 = *(const float4*)&Sa[uu][tm];
            float4 b4 = *(const float4*)&Sb[uu][tn];
            float a[4]  = {a4.x, a4.y, a4.z, a4.w};
            float bb[4] = {b4.x, b4.y, b4.z, b4.w};
#pragma unroll
            for (int i = 0; i < 4; ++i)
#pragma unroll
                for (int j = 0; j < 4; ++j)
                    acc[i][j] = fmaf(a[i], bb[j], acc[i][j]);
        }
        __syncthreads();
    }

    for (int d0 = 0; d0 < DD; d0 += 16) {
        {
            const float qsc = g_powL[s0 + lrow + 1];
            float4 qa = *(const float4*)(qg + (size_t)(s0 + lrow) * DD + d0 + ld4);
            Sa[ld4 + 0][lrow] = qa.x * qsc;
            Sa[ld4 + 1][lrow] = qa.y * qsc;
            Sa[ld4 + 2][lrow] = qa.z * qsc;
            Sa[ld4 + 3][lrow] = qa.w * qsc;
            float4 aa = *(const float4*)(ab + (size_t)(d0 + srow) * DD + j0 + sc4);
            *(float4*)&Sb[srow][sc4] = aa;
        }
        __syncthreads();

#pragma unroll
        for (int dd = 0; dd < 16; ++dd) {
            float4 a4 = *(const float4*)&Sa[dd][tm];
            float4 b4 = *(const float4*)&Sb[dd][tn];
            float a[4]  = {a4.x, a4.y, a4.z, a4.w};
            float bb[4] = {b4.x, b4.y, b4.z, b4.w};
#pragma unroll
            for (int i = 0; i < 4; ++i)
#pragma unroll
                for (int j = 0; j < 4; ++j)
                    acc[i][j] = fmaf(a[i], bb[j], acc[i][j]);
        }
        __syncthreads();
    }

    float* dst = g_y + (size_t)b * LSEQ * DD + (size_t)t0 * DD;
#pragma unroll
    for (int i = 0; i < 4; ++i)
        *(float4*)(dst + (size_t)(s0 + tm + i) * DD + j0 + tn) =
            make_float4(acc[i][0], acc[i][1], acc[i][2], acc[i][3]);
}

// ===========================================================================
// Launch. Inputs: 0:x 1:state 2:Wk 3:bk 4:Wv 5:bv 6:Wq 7:bq 8:Wo 9:bo
// Output: out (B*L*D floats) followed by final_state (B*D*D floats).
// ===========================================================================
extern "C" void kernel_launch(void* const* d_in, const int* in_sizes, int n_in,
                              void* d_out, int out_size)
{
    const float* x     = (const float*)d_in[0];
    const float* state = (const float*)d_in[1];
    const float* Wk    = (const float*)d_in[2];
    const float* bk    = (const float*)d_in[3];
    const float* Wv    = (const float*)d_in[4];
    const float* bv    = (const float*)d_in[5];
    const float* Wq    = (const float*)d_in[6];
    const float* bq    = (const float*)d_in[7];
    const float* Wo    = (const float*)d_in[8];
    const float* bo    = (const float*)d_in[9];

    float* out    = (float*)d_out;
    float* fstate = out + (size_t)MTOT * DD;

    cudaFuncSetAttribute(mma_gemm,
                         cudaFuncAttributeMaxDynamicSharedMemorySize, TB_SMEM);

    pow_kernel<<<1, 32>>>();

    dim3 tc_grid(MTOT / 128, DD / 128);           // (256, 2)
    mma_gemm<<<tc_grid, 256, TB_SMEM>>>(x, Wk, bk, nullptr, 0);   // -> g_k
    mma_gemm<<<tc_grid, 256, TB_SMEM>>>(x, Wv, bv, nullptr, 1);   // -> g_v
    mma_gemm<<<tc_grid, 256, TB_SMEM>>>(x, Wq, bq, nullptr, 2);   // -> g_q

    dA_kernel<<<dim3(4, 4, NCHG), 256>>>();       // per-chunk K'^T V

    prefix_kernel<<<dim3(16, BB), 256>>>(state, fstate);

    p_kernel<<<dim3(2, 2, NCHG), 256>>>();        // masked decay QK^T

    y_kernel<<<dim3(2, 4, NCHG), 256>>>();        // P V + (lam^(s+1) Q) A_base

    mma_gemm<<<tc_grid, 256, TB_SMEM>>>(nullptr, Wo, bo, out, 3); // g_y -> out
}

// round 16
// speedup vs baseline: 7.9957x; 1.3178x over previous
#include <cuda_runtime.h>
#include <cuda_bf16.h>
#include <cstdint>

// Problem constants
#define BB    8
#define LSEQ  4096
#define DD    256
#define MTOT  (BB * LSEQ)          // 32768 rows for the projection GEMMs

constexpr float DECAY = 0.9f;
constexpr float LR    = 0.1f;
constexpr int   CS    = 128;               // chunk size S
constexpr int   NCH   = LSEQ / CS;         // 32 chunks per batch
constexpr int   NCHG  = NCH * BB;          // 256 chunk-units total

// Scratch (allocation-free rule: __device__ globals).
// Device-code references ONLY — passing these as host-side kernel args gives a
// bogus symbol address (R11 failure).
__device__ float g_k[MTOT * DD];
__device__ float g_v[MTOT * DD];
__device__ float g_q[MTOT * DD];
__device__ float g_y[MTOT * DD];
__device__ float g_dA[NCHG * DD * DD];     // per-chunk state increments
__device__ float g_Ab[NCHG * DD * DD];     // per-chunk A_base checkpoints
__device__ float g_P[NCHG * CS * CS];      // per-chunk masked attention
__device__ float g_powL[132];              // DECAY^0 .. DECAY^129

// ===========================================================================
// mma.sync helpers (plain sm_80+ PTX; tcgen05 is rejected for target sm_103)
// ===========================================================================
__device__ __forceinline__ void ldmx4(uint32_t& r0, uint32_t& r1,
                                      uint32_t& r2, uint32_t& r3, uint32_t addr)
{
    asm volatile("ldmatrix.sync.aligned.m8n8.x4.shared.b16 {%0,%1,%2,%3}, [%4];"
                 : "=r"(r0), "=r"(r1), "=r"(r2), "=r"(r3) : "r"(addr));
}
__device__ __forceinline__ void ldmx4t(uint32_t& r0, uint32_t& r1,
                                       uint32_t& r2, uint32_t& r3, uint32_t addr)
{
    asm volatile("ldmatrix.sync.aligned.m8n8.x4.trans.shared.b16 {%0,%1,%2,%3}, [%4];"
                 : "=r"(r0), "=r"(r1), "=r"(r2), "=r"(r3) : "r"(addr));
}
__device__ __forceinline__ void mma16816(float* c, const uint32_t* a,
                                         const uint32_t* b)
{
    asm volatile(
        "mma.sync.aligned.m16n8k16.row.col.f32.bf16.bf16.f32 "
        "{%0,%1,%2,%3}, {%4,%5,%6,%7}, {%8,%9}, {%0,%1,%2,%3};"
        : "+f"(c[0]), "+f"(c[1]), "+f"(c[2]), "+f"(c[3])
        : "r"(a[0]), "r"(a[1]), "r"(a[2]), "r"(a[3]), "r"(b[0]), "r"(b[1]));
}
__device__ __forceinline__ uint32_t smem_to_u32(const void* p) {
    uint32_t a;
    asm("{ .reg .u64 t; cvta.to.shared.u64 t, %1; cvt.u32.u64 %0, t; }"
        : "=r"(a) : "l"(p));
    return a;
}

// scale-then-split fp32 -> (hi bf16, lo bf16), 8 at a time, packed 2-per-u32
__device__ __forceinline__ void split8s(const float* __restrict__ g, float sc,
                                        uint4& hi, uint4& lo)
{
    float4 f0 = *(const float4*)g;
    float4 f1 = *(const float4*)(g + 4);
    float f[8] = {f0.x * sc, f0.y * sc, f0.z * sc, f0.w * sc,
                  f1.x * sc, f1.y * sc, f1.z * sc, f1.w * sc};
    unsigned short hs[8], ls[8];
#pragma unroll
    for (int i = 0; i < 8; ++i) {
        __nv_bfloat16 h = __float2bfloat16_rn(f[i]);
        hs[i] = __bfloat16_as_ushort(h);
        float r = f[i] - __bfloat162float(h);
        ls[i] = __bfloat16_as_ushort(__float2bfloat16_rn(r));
    }
    hi.x = (uint32_t)hs[0] | ((uint32_t)hs[1] << 16);
    hi.y = (uint32_t)hs[2] | ((uint32_t)hs[3] << 16);
    hi.z = (uint32_t)hs[4] | ((uint32_t)hs[5] << 16);
    hi.w = (uint32_t)hs[6] | ((uint32_t)hs[7] << 16);
    lo.x = (uint32_t)ls[0] | ((uint32_t)ls[1] << 16);
    lo.y = (uint32_t)ls[2] | ((uint32_t)ls[3] << 16);
    lo.z = (uint32_t)ls[4] | ((uint32_t)ls[5] << 16);
    lo.w = (uint32_t)ls[6] | ((uint32_t)ls[7] << 16);
}

// ===========================================================================
// Kernel 0: decay power table (serial multiply, matches reference rounding)
// ===========================================================================
__global__ void pow_kernel() {
    if (threadIdx.x == 0 && blockIdx.x == 0) {
        float p = 1.0f;
        for (int i = 0; i <= 130; ++i) { g_powL[i] = p; p *= DECAY; }
    }
}

// ===========================================================================
// mma_gemm: C[m][n] = sum_d A[m][d] * W[n][d] + bias[n]   (PROVEN in R12)
// dst_sel: 0->C=g_k, 1->g_v, 2->g_q (A=A_ext);  3->C=C_ext, A=g_y.
// ===========================================================================
constexpr int ROWB    = 144;        // A-side smem row stride (72 halves)
constexpr int TB_AHI  = 0;
constexpr int TB_ALO  = 18432;      // 128*144
constexpr int TB_WHI  = 36864;
constexpr int TB_WLO  = 55296;
constexpr int TB_SMEM = 73728;

__global__ __launch_bounds__(256) void mma_gemm(
    const float* __restrict__ A_ext, const float* __restrict__ W,
    const float* __restrict__ bias, float* __restrict__ C_ext, int dst_sel)
{
    extern __shared__ char sm[];
    const uint32_t sb = smem_to_u32(sm);
    const int tid  = threadIdx.x;
    const int wid  = tid >> 5;
    const int lane = tid & 31;
    const size_t m0 = (size_t)blockIdx.x * 128;
    const int    n0 = blockIdx.y * 128;
    const int warpM = wid >> 2;
    const int warpN = wid & 3;

    const float* A = (dst_sel == 3) ? g_y : A_ext;
    float* C;
    switch (dst_sel) {
        case 0:  C = g_k;   break;
        case 1:  C = g_v;   break;
        case 2:  C = g_q;   break;
        default: C = C_ext; break;
    }

    float acc[4][4][4];
#pragma unroll
    for (int mf = 0; mf < 4; ++mf)
#pragma unroll
        for (int nf = 0; nf < 4; ++nf)
#pragma unroll
            for (int i = 0; i < 4; ++i) acc[mf][nf][i] = 0.0f;

    const int arow  = warpM * 64 + (lane & 15);
    const int acolh = (lane >> 4) * 8;
    const int brow  = warpN * 32 + ((lane >> 4) << 3) + (lane & 7);
    const int bcolh = (lane & 8);

    for (int ks = 0; ks < 4; ++ks) {
        const int k0 = ks * 64;
#pragma unroll
        for (int c = 0; c < 4; ++c) {
            const int ci  = tid + c * 256;
            const int row = ci >> 3;
            const int c8  = ci & 7;
            uint4 hi, lo;
            split8s(A + (m0 + row) * DD + k0 + c8 * 8, 1.0f, hi, lo);
            *(uint4*)(sm + TB_AHI + row * ROWB + c8 * 16) = hi;
            *(uint4*)(sm + TB_ALO + row * ROWB + c8 * 16) = lo;
            split8s(W + (size_t)(n0 + row) * DD + k0 + c8 * 8, 1.0f, hi, lo);
            *(uint4*)(sm + TB_WHI + row * ROWB + c8 * 16) = hi;
            *(uint4*)(sm + TB_WLO + row * ROWB + c8 * 16) = lo;
        }
        __syncthreads();

        const uint32_t abufs[3] = {sb + TB_AHI, sb + TB_AHI, sb + TB_ALO};
        const uint32_t bbufs[3] = {sb + TB_WHI, sb + TB_WLO, sb + TB_WHI};
#pragma unroll
        for (int pass = 0; pass < 3; ++pass) {
#pragma unroll
            for (int k16 = 0; k16 < 4; ++k16) {
                uint32_t af[4][4];
#pragma unroll
                for (int mf = 0; mf < 4; ++mf) {
                    const uint32_t addr = abufs[pass] +
                        (uint32_t)(arow + mf * 16) * ROWB +
                        (uint32_t)(k16 * 16 + acolh) * 2;
                    ldmx4(af[mf][0], af[mf][1], af[mf][2], af[mf][3], addr);
                }
                uint32_t bf[4][2];
#pragma unroll
                for (int p = 0; p < 2; ++p) {
                    const uint32_t addr = bbufs[pass] +
                        (uint32_t)(brow + p * 16) * ROWB +
                        (uint32_t)(k16 * 16 + bcolh) * 2;
                    uint32_t r0, r1, r2, r3;
                    ldmx4(r0, r1, r2, r3, addr);
                    bf[2 * p][0]     = r0;  bf[2 * p][1]     = r1;
                    bf[2 * p + 1][0] = r2;  bf[2 * p + 1][1] = r3;
                }
#pragma unroll
                for (int mf = 0; mf < 4; ++mf)
#pragma unroll
                    for (int nf = 0; nf < 4; ++nf)
                        mma16816(acc[mf][nf], af[mf], bf[nf]);
            }
        }
        __syncthreads();
    }

    const int gid = lane >> 2;
    const int tig = lane & 3;
#pragma unroll
    for (int mf = 0; mf < 4; ++mf) {
        const size_t r0 = m0 + warpM * 64 + mf * 16 + gid;
#pragma unroll
        for (int nf = 0; nf < 4; ++nf) {
            const int cb = n0 + warpN * 32 + nf * 8 + tig * 2;
            const float b0 = __ldg(bias + cb);
            const float b1 = __ldg(bias + cb + 1);
            *(float2*)(C + r0 * DD + cb) =
                make_float2(acc[mf][nf][0] + b0, acc[mf][nf][1] + b1);
            *(float2*)(C + (r0 + 8) * DD + cb) =
                make_float2(acc[mf][nf][2] + b0, acc[mf][nf][3] + b1);
        }
    }
}

// ===========================================================================
// dA_mma: dA[g][i][j] = sum_u (eta*lambda^{CS-1-u} k[u][i]) * v[u][j]
// Contraction u = ROW dim of both operands -> direct-copy staging, BOTH
// fragments via ldmatrix.trans. B-side row stride 272B (bank-shift 4, clean).
// CTA 128x128, grid (2,2,NCHG); K=128 in 2 slices of 64.
// ===========================================================================
constexpr int TROWB   = 272;        // 128 halves + 8 pad
constexpr int DA_KHI  = 0;
constexpr int DA_KLO  = 17408;      // 64*272
constexpr int DA_VHI  = 34816;
constexpr int DA_VLO  = 52224;
constexpr int DA_SMEM = 69632;

__global__ __launch_bounds__(256) void dA_mma()
{
    extern __shared__ char sm[];
    const uint32_t sb = smem_to_u32(sm);
    const int g   = blockIdx.z;
    const int b   = g >> 5;
    const int c   = g & 31;
    const int i0  = blockIdx.x * 128;
    const int j0  = blockIdx.y * 128;
    const int tid = threadIdx.x;
    const int wid = tid >> 5;
    const int lane = tid & 31;
    const int warpM = wid >> 2;
    const int warpN = wid & 3;
    const int t0  = c * CS;

    const float* kg = g_k + (size_t)b * LSEQ * DD + (size_t)t0 * DD;
    const float* vg = g_v + (size_t)b * LSEQ * DD + (size_t)t0 * DD;

    float acc[4][4][4];
#pragma unroll
    for (int mf = 0; mf < 4; ++mf)
#pragma unroll
        for (int nf = 0; nf < 4; ++nf)
#pragma unroll
            for (int i = 0; i < 4; ++i) acc[mf][nf][i] = 0.0f;

    // .trans lane addressing (x4 groups -> a0..a3 / b pairs)
    const int at_row  = (lane & 7) + ((lane >> 4) << 3);   // k-row
    const int at_colh = warpM * 64 + ((lane >> 3) & 1) * 8; // + mf*16 (m cols)
    const int bt_row  = (lane & 7) + ((lane >> 3) & 1) * 8; // k-row
    const int bt_colh = warpN * 32 + ((lane >> 4) & 1) * 8; // + p*16 (n cols)

    for (int us = 0; us < 2; ++us) {
        const int u0 = us * 64;
#pragma unroll
        for (int cc = 0; cc < 4; ++cc) {
            const int ci  = tid + cc * 256;      // 0..1023
            const int row = ci >> 4;             // 0..63 (u within slice)
            const int c8  = ci & 15;             // 16 chunks of 8 halves
            const int u   = u0 + row;
            const float ksc = LR * g_powL[CS - 1 - u];
            uint4 hi, lo;
            split8s(kg + (size_t)u * DD + i0 + c8 * 8, ksc, hi, lo);
            *(uint4*)(sm + DA_KHI + row * TROWB + c8 * 16) = hi;
            *(uint4*)(sm + DA_KLO + row * TROWB + c8 * 16) = lo;
            split8s(vg + (size_t)u * DD + j0 + c8 * 8, 1.0f, hi, lo);
            *(uint4*)(sm + DA_VHI + row * TROWB + c8 * 16) = hi;
            *(uint4*)(sm + DA_VLO + row * TROWB + c8 * 16) = lo;
        }
        __syncthreads();

        const uint32_t abufs[3] = {sb + DA_KHI, sb + DA_KHI, sb + DA_KLO};
        const uint32_t bbufs[3] = {sb + DA_VHI, sb + DA_VLO, sb + DA_VHI};
#pragma unroll
        for (int pass = 0; pass < 3; ++pass) {
#pragma unroll
            for (int k16 = 0; k16 < 4; ++k16) {
                uint32_t af[4][4];
#pragma unroll
                for (int mf = 0; mf < 4; ++mf) {
                    const uint32_t addr = abufs[pass] +
                        (uint32_t)(at_row + k16 * 16) * TROWB +
                        (uint32_t)(at_colh + mf * 16) * 2;
                    ldmx4t(af[mf][0], af[mf][1], af[mf][2], af[mf][3], addr);
                }
                uint32_t bf[4][2];
#pragma unroll
                for (int p = 0; p < 2; ++p) {
                    const uint32_t addr = bbufs[pass] +
                        (uint32_t)(bt_row + k16 * 16) * TROWB +
                        (uint32_t)(bt_colh + p * 16) * 2;
                    uint32_t r0, r1, r2, r3;
                    ldmx4t(r0, r1, r2, r3, addr);
                    bf[2 * p][0]     = r0;  bf[2 * p][1]     = r1;
                    bf[2 * p + 1][0] = r2;  bf[2 * p + 1][1] = r3;
                }
#pragma unroll
                for (int mf = 0; mf < 4; ++mf)
#pragma unroll
                    for (int nf = 0; nf < 4; ++nf)
                        mma16816(acc[mf][nf], af[mf], bf[nf]);
            }
        }
        __syncthreads();
    }

    float* dst = g_dA + (size_t)g * DD * DD;
    const int gid = lane >> 2;
    const int tig = lane & 3;
#pragma unroll
    for (int mf = 0; mf < 4; ++mf) {
        const int r0 = i0 + warpM * 64 + mf * 16 + gid;
#pragma unroll
        for (int nf = 0; nf < 4; ++nf) {
            const int cb = j0 + warpN * 32 + nf * 8 + tig * 2;
            *(float2*)(dst + (size_t)r0 * DD + cb) =
                make_float2(acc[mf][nf][0], acc[mf][nf][1]);
            *(float2*)(dst + (size_t)(r0 + 8) * DD + cb) =
                make_float2(acc[mf][nf][2], acc[mf][nf][3]);
        }
    }
}

// ===========================================================================
// Kernel 3: serial prefix over chunks (element-parallel, DRAM-bound, 32us).
// ===========================================================================
__global__ __launch_bounds__(256) void prefix_kernel(
    const float* __restrict__ state, float* __restrict__ fstate)
{
    const int b  = blockIdx.y;
    const int e0 = (blockIdx.x * 256 + threadIdx.x) * 16;
    const float lamS = g_powL[CS];

    float4 a[4];
#pragma unroll
    for (int i = 0; i < 4; ++i)
        a[i] = *(const float4*)(state + (size_t)b * DD * DD + e0 + i * 4);

    for (int c = 0; c < NCH; ++c) {
        float* ab = g_Ab + ((size_t)(b * NCH + c)) * DD * DD + e0;
        const float* da = g_dA + ((size_t)(b * NCH + c)) * DD * DD + e0;
#pragma unroll
        for (int i = 0; i < 4; ++i) {
            *(float4*)(ab + i * 4) = a[i];
            float4 d = *(const float4*)(da + i * 4);
            a[i].x = fmaf(lamS, a[i].x, d.x);
            a[i].y = fmaf(lamS, a[i].y, d.y);
            a[i].z = fmaf(lamS, a[i].z, d.z);
            a[i].w = fmaf(lamS, a[i].w, d.w);
        }
    }
#pragma unroll
    for (int i = 0; i < 4; ++i)
        *(float4*)(fstate + (size_t)b * DD * DD + e0 + i * 4) = a[i];
}

// ===========================================================================
// p_mma: P[g][s][u] = (u<=s) ? eta*lambda^(s-u)*dot(q_s,k_u) : 0
// Q and K both contraction-contiguous -> exact mma_gemm structure (normal
// ldmatrix), masked/decayed epilogue. CTA 128x128 = full chunk; grid NCHG.
// ===========================================================================
__global__ __launch_bounds__(256) void p_mma()
{
    extern __shared__ char sm[];
    const uint32_t sb = smem_to_u32(sm);
    const int g   = blockIdx.x;
    const int b   = g >> 5;
    const int c   = g & 31;
    const int tid = threadIdx.x;
    const int wid = tid >> 5;
    const int lane = tid & 31;
    const int warpM = wid >> 2;
    const int warpN = wid & 3;
    const int t0  = c * CS;

    const float* qg = g_q + (size_t)b * LSEQ * DD + (size_t)t0 * DD;
    const float* kg = g_k + (size_t)b * LSEQ * DD + (size_t)t0 * DD;

    float acc[4][4][4];
#pragma unroll
    for (int mf = 0; mf < 4; ++mf)
#pragma unroll
        for (int nf = 0; nf < 4; ++nf)
#pragma unroll
            for (int i = 0; i < 4; ++i) acc[mf][nf][i] = 0.0f;

    const int arow  = warpM * 64 + (lane & 15);
    const int acolh = (lane >> 4) * 8;
    const int brow  = warpN * 32 + ((lane >> 4) << 3) + (lane & 7);
    const int bcolh = (lane & 8);

    for (int ks = 0; ks < 4; ++ks) {
        const int k0 = ks * 64;
#pragma unroll
        for (int cc = 0; cc < 4; ++cc) {
            const int ci  = tid + cc * 256;
            const int row = ci >> 3;
            const int c8  = ci & 7;
            uint4 hi, lo;
            split8s(qg + (size_t)row * DD + k0 + c8 * 8, 1.0f, hi, lo);
            *(uint4*)(sm + TB_AHI + row * ROWB + c8 * 16) = hi;
            *(uint4*)(sm + TB_ALO + row * ROWB + c8 * 16) = lo;
            split8s(kg + (size_t)row * DD + k0 + c8 * 8, 1.0f, hi, lo);
            *(uint4*)(sm + TB_WHI + row * ROWB + c8 * 16) = hi;
            *(uint4*)(sm + TB_WLO + row * ROWB + c8 * 16) = lo;
        }
        __syncthreads();

        const uint32_t abufs[3] = {sb + TB_AHI, sb + TB_AHI, sb + TB_ALO};
        const uint32_t bbufs[3] = {sb + TB_WHI, sb + TB_WLO, sb + TB_WHI};
#pragma unroll
        for (int pass = 0; pass < 3; ++pass) {
#pragma unroll
            for (int k16 = 0; k16 < 4; ++k16) {
                uint32_t af[4][4];
#pragma unroll
                for (int mf = 0; mf < 4; ++mf) {
                    const uint32_t addr = abufs[pass] +
                        (uint32_t)(arow + mf * 16) * ROWB +
                        (uint32_t)(k16 * 16 + acolh) * 2;
                    ldmx4(af[mf][0], af[mf][1], af[mf][2], af[mf][3], addr);
                }
                uint32_t bf[4][2];
#pragma unroll
                for (int p = 0; p < 2; ++p) {
                    const uint32_t addr = bbufs[pass] +
                        (uint32_t)(brow + p * 16) * ROWB +
                        (uint32_t)(k16 * 16 + bcolh) * 2;
                    uint32_t r0, r1, r2, r3;
                    ldmx4(r0, r1, r2, r3, addr);
                    bf[2 * p][0]     = r0;  bf[2 * p][1]     = r1;
                    bf[2 * p + 1][0] = r2;  bf[2 * p + 1][1] = r3;
                }
#pragma unroll
                for (int mf = 0; mf < 4; ++mf)
#pragma unroll
                    for (int nf = 0; nf < 4; ++nf)
                        mma16816(acc[mf][nf], af[mf], bf[nf]);
            }
        }
        __syncthreads();
    }

    float* dst = g_P + (size_t)g * CS * CS;
    const int gid = lane >> 2;
    const int tig = lane & 3;
#pragma unroll
    for (int mf = 0; mf < 4; ++mf) {
#pragma unroll
        for (int half = 0; half < 2; ++half) {
            const int s = warpM * 64 + mf * 16 + half * 8 + gid;
#pragma unroll
            for (int nf = 0; nf < 4; ++nf) {
                const int u0 = warpN * 32 + nf * 8 + tig * 2;
                float v0 = acc[mf][nf][2 * half + 0];
                float v1 = acc[mf][nf][2 * half + 1];
                v0 = (u0     <= s) ? v0 * LR * g_powL[s - u0]     : 0.0f;
                v1 = (u0 + 1 <= s) ? v1 * LR * g_powL[s - u0 - 1] : 0.0f;
                *(float2*)(dst + (size_t)s * CS + u0) = make_float2(v0, v1);
            }
        }
    }
}

// ===========================================================================
// y_mma: Y[s][j] = sum_u P[s][u]*V[u][j] + sum_d (lam^{s+1} Q[s][d])*Ab[d][j]
// Phase 1: A=P normal, B=V trans (2 slices of u). Phase 2: A=Q scaled normal,
// B=Ab trans (4 slices of d). One accumulator. CTA 128x128; grid (2, NCHG).
// ===========================================================================
constexpr int Y_AHI  = 0;
constexpr int Y_ALO  = 18432;
constexpr int Y_BHI  = 36864;           // 64 rows * 272B = 17408
constexpr int Y_BLO  = 54272;
constexpr int Y_SMEM = 71680;

__global__ __launch_bounds__(256) void y_mma()
{
    extern __shared__ char sm[];
    const uint32_t sb = smem_to_u32(sm);
    const int g   = blockIdx.y;
    const int b   = g >> 5;
    const int c   = g & 31;
    const int j0  = blockIdx.x * 128;
    const int tid = threadIdx.x;
    const int wid = tid >> 5;
    const int lane = tid & 31;
    const int warpM = wid >> 2;
    const int warpN = wid & 3;
    const int t0  = c * CS;

    const float* pg = g_P + (size_t)g * CS * CS;
    const float* vg = g_v + (size_t)b * LSEQ * DD + (size_t)t0 * DD;
    const float* qg = g_q + (size_t)b * LSEQ * DD + (size_t)t0 * DD;
    const float* ab = g_Ab + (size_t)g * DD * DD;

    float acc[4][4][4];
#pragma unroll
    for (int mf = 0; mf < 4; ++mf)
#pragma unroll
        for (int nf = 0; nf < 4; ++nf)
#pragma unroll
            for (int i = 0; i < 4; ++i) acc[mf][nf][i] = 0.0f;

    const int arow  = warpM * 64 + (lane & 15);
    const int acolh = (lane >> 4) * 8;
    const int bt_row  = (lane & 7) + ((lane >> 3) & 1) * 8;
    const int bt_colh = warpN * 32 + ((lane >> 4) & 1) * 8;

    // 6 K-slices: slice 0-1 = P*V (u), slice 2-5 = Q'*Ab (d)
    for (int sl = 0; sl < 6; ++sl) {
        const bool ph1 = (sl < 2);
        const int  k0  = ph1 ? sl * 64 : (sl - 2) * 64;
        // ---- stage A (128 rows x 64 halves, ROWB) ----
#pragma unroll
        for (int cc = 0; cc < 4; ++cc) {
            const int ci  = tid + cc * 256;
            const int row = ci >> 3;            // s
            const int c8  = ci & 7;
            uint4 hi, lo;
            if (ph1) {
                split8s(pg + (size_t)row * CS + k0 + c8 * 8, 1.0f, hi, lo);
            } else {
                const float qsc = g_powL[row + 1];
                split8s(qg + (size_t)row * DD + k0 + c8 * 8, qsc, hi, lo);
            }
            *(uint4*)(sm + Y_AHI + row * ROWB + c8 * 16) = hi;
            *(uint4*)(sm + Y_ALO + row * ROWB + c8 * 16) = lo;
        }
        // ---- stage B (64 rows x 128 halves, TROWB) ----
#pragma unroll
        for (int cc = 0; cc < 4; ++cc) {
            const int ci  = tid + cc * 256;
            const int row = ci >> 4;            // k-row within slice
            const int c8  = ci & 15;
            uint4 hi, lo;
            if (ph1) {
                split8s(vg + (size_t)(k0 + row) * DD + j0 + c8 * 8, 1.0f, hi, lo);
            } else {
                split8s(ab + (size_t)(k0 + row) * DD + j0 + c8 * 8, 1.0f, hi, lo);
            }
            *(uint4*)(sm + Y_BHI + row * TROWB + c8 * 16) = hi;
            *(uint4*)(sm + Y_BLO + row * TROWB + c8 * 16) = lo;
        }
        __syncthreads();

        const uint32_t abufs[3] = {sb + Y_AHI, sb + Y_AHI, sb + Y_ALO};
        const uint32_t bbufs[3] = {sb + Y_BHI, sb + Y_BLO, sb + Y_BHI};
#pragma unroll
        for (int pass = 0; pass < 3; ++pass) {
#pragma unroll
            for (int k16 = 0; k16 < 4; ++k16) {
                uint32_t af[4][4];
#pragma unroll
                for (int mf = 0; mf < 4; ++mf) {
                    const uint32_t addr = abufs[pass] +
                        (uint32_t)(arow + mf * 16) * ROWB +
                        (uint32_t)(k16 * 16 + acolh) * 2;
                    ldmx4(af[mf][0], af[mf][1], af[mf][2], af[mf][3], addr);
                }
                uint32_t bf[4][2];
#pragma unroll
                for (int p = 0; p < 2; ++p) {
                    const uint32_t addr = bbufs[pass] +
                        (uint32_t)(bt_row + k16 * 16) * TROWB +
                        (uint32_t)(bt_colh + p * 16) * 2;
                    uint32_t r0, r1, r2, r3;
                    ldmx4t(r0, r1, r2, r3, addr);
                    bf[2 * p][0]     = r0;  bf[2 * p][1]     = r1;
                    bf[2 * p + 1][0] = r2;  bf[2 * p + 1][1] = r3;
                }
#pragma unroll
                for (int mf = 0; mf < 4; ++mf)
#pragma unroll
                    for (int nf = 0; nf < 4; ++nf)
                        mma16816(acc[mf][nf], af[mf], bf[nf]);
            }
        }
        __syncthreads();
    }

    float* dst = g_y + (size_t)b * LSEQ * DD + (size_t)t0 * DD;
    const int gid = lane >> 2;
    const int tig = lane & 3;
#pragma unroll
    for (int mf = 0; mf < 4; ++mf) {
        const int r0 = warpM * 64 + mf * 16 + gid;
#pragma unroll
        for (int nf = 0; nf < 4; ++nf) {
            const int cb = j0 + warpN * 32 + nf * 8 + tig * 2;
            *(float2*)(dst + (size_t)r0 * DD + cb) =
                make_float2(acc[mf][nf][0], acc[mf][nf][1]);
            *(float2*)(dst + (size_t)(r0 + 8) * DD + cb) =
                make_float2(acc[mf][nf][2], acc[mf][nf][3]);
        }
    }
}

// ===========================================================================
// Launch. Inputs: 0:x 1:state 2:Wk 3:bk 4:Wv 5:bv 6:Wq 7:bq 8:Wo 9:bo
// Output: out (B*L*D floats) followed by final_state (B*D*D floats).
// ===========================================================================
extern "C" void kernel_launch(void* const* d_in, const int* in_sizes, int n_in,
                              void* d_out, int out_size)
{
    const float* x     = (const float*)d_in[0];
    const float* state = (const float*)d_in[1];
    const float* Wk    = (const float*)d_in[2];
    const float* bk    = (const float*)d_in[3];
    const float* Wv    = (const float*)d_in[4];
    const float* bv    = (const float*)d_in[5];
    const float* Wq    = (const float*)d_in[6];
    const float* bq    = (const float*)d_in[7];
    const float* Wo    = (const float*)d_in[8];
    const float* bo    = (const float*)d_in[9];

    float* out    = (float*)d_out;
    float* fstate = out + (size_t)MTOT * DD;

    cudaFuncSetAttribute(mma_gemm,
                         cudaFuncAttributeMaxDynamicSharedMemorySize, TB_SMEM);
    cudaFuncSetAttribute(dA_mma,
                         cudaFuncAttributeMaxDynamicSharedMemorySize, DA_SMEM);
    cudaFuncSetAttribute(p_mma,
                         cudaFuncAttributeMaxDynamicSharedMemorySize, TB_SMEM);
    cudaFuncSetAttribute(y_mma,
                         cudaFuncAttributeMaxDynamicSharedMemorySize, Y_SMEM);

    pow_kernel<<<1, 32>>>();

    dim3 tc_grid(MTOT / 128, DD / 128);           // (256, 2)
    mma_gemm<<<tc_grid, 256, TB_SMEM>>>(x, Wk, bk, nullptr, 0);   // -> g_k
    mma_gemm<<<tc_grid, 256, TB_SMEM>>>(x, Wv, bv, nullptr, 1);   // -> g_v
    mma_gemm<<<tc_grid, 256, TB_SMEM>>>(x, Wq, bq, nullptr, 2);   // -> g_q

    dA_mma<<<dim3(2, 2, NCHG), 256, DA_SMEM>>>(); // per-chunk K'^T V

    prefix_kernel<<<dim3(16, BB), 256>>>(state, fstate);

    p_mma<<<NCHG, 256, TB_SMEM>>>();              // masked decay QK^T

    y_mma<<<dim3(2, NCHG), 256, Y_SMEM>>>();      // P V + (lam^(s+1) Q) Ab

    mma_gemm<<<tc_grid, 256, TB_SMEM>>>(nullptr, Wo, bo, out, 3); // g_y -> out
}